// round 1
// baseline (speedup 1.0000x reference)
#include <cuda_runtime.h>
#include <math.h>

#define BS_    128
#define SEQ    32
#define DIMN   512
#define P_     10
#define NTOP   6

// ---------------- scratch (device globals; no allocations allowed) ----------
__device__ float g_X [BS_ * SEQ * DIMN];    // x stored as (b, s, d)  == att_out
__device__ float g_Y1[BS_ * SEQ * DIMN];    // conv intermediate (b, s, d)
__device__ float g_psl[BS_ * 2 * P_ * DIMN];// psl_all (b, 20, d)

// ---------------- generic tiled fp32 GEMM:  C[M x 512] = A[M x K] * B[512 x K]^T + bias
// Block tile 128(M) x 64(N), BK=8, 256 threads, thread tile 8x4.
// AMODE 0: plain row-major A (lda param)
// AMODE 1: im2col conv1d k=5 pad=2 over s; A is (b, s, din) fp32, relu applied;
//          k index = din*5 + tap  (matches res_w[dout][din][tap] contiguous rows)
// AMODE 2: concat(obj, motion) rows of 1024 (A = obj, A2 = motion)
// EPI 0: C = acc + bias ; EPI 1: C = C + 0.3f*(acc + bias)
#define BM 128
#define BN 64
#define BK 8

template<int AMODE, int EPI>
__global__ void __launch_bounds__(256) gemm_kernel(
    const float* __restrict__ A, const float* __restrict__ A2,
    const float* __restrict__ B, const float* __restrict__ bias,
    float* __restrict__ C, int M, int K, int lda)
{
    __shared__ float As[BK][BM + 4];
    __shared__ float Bs[BK][BN + 4];
    const int t    = threadIdx.x;
    const int row0 = blockIdx.y * BM;
    const int col0 = blockIdx.x * BN;
    const int tx   = t & 15;   // n direction
    const int ty   = t >> 4;   // m direction

    float acc[8][4];
#pragma unroll
    for (int i = 0; i < 8; i++)
#pragma unroll
        for (int j = 0; j < 4; j++) acc[i][j] = 0.f;

    for (int k0 = 0; k0 < K; k0 += BK) {
        // ---- load A tile (128 rows x 8 k), transposed into As[k][m] ----
        if (AMODE == 1) {
            const int arow = t & 127;
            const int ak0  = (t >> 7) * 4;
            const int grow = row0 + arow;
            const int bb   = grow >> 5;
            const int s    = grow & 31;
#pragma unroll
            for (int i = 0; i < 4; i++) {
                const int kk  = k0 + ak0 + i;
                const int din = kk / 5;
                const int tap = kk - din * 5;
                const int s2  = s + tap - 2;
                float v = 0.f;
                if (s2 >= 0 && s2 < SEQ) {
                    v = A[((size_t)(bb * SEQ + s2)) * DIMN + din];
                    v = v > 0.f ? v : 0.f;
                }
                As[ak0 + i][arow] = v;
            }
        } else {
            const int arow = t >> 1;
            const int ak   = (t & 1) * 4;
            const float* src;
            if (AMODE == 2) {
                const int grow = row0 + arow;
                const int b    = grow / 20;
                const int p    = grow - b * 20;
                src = (p < P_) ? (A  + ((size_t)(b * P_ + p       )) * 1024 + k0 + ak)
                               : (A2 + ((size_t)(b * P_ + p - P_  )) * 1024 + k0 + ak);
            } else {
                src = A + (size_t)(row0 + arow) * lda + k0 + ak;
            }
            const float4 v = *(const float4*)src;
            As[ak    ][arow] = v.x;
            As[ak + 1][arow] = v.y;
            As[ak + 2][arow] = v.z;
            As[ak + 3][arow] = v.w;
        }
        // ---- load B tile (64 rows x 8 k), transposed into Bs[k][n] ----
        if (t < 128) {
            const int brow = t >> 1;
            const int bk   = (t & 1) * 4;
            const float4 v = *(const float4*)(B + (size_t)(col0 + brow) * K + k0 + bk);
            Bs[bk    ][brow] = v.x;
            Bs[bk + 1][brow] = v.y;
            Bs[bk + 2][brow] = v.z;
            Bs[bk + 3][brow] = v.w;
        }
        __syncthreads();
#pragma unroll
        for (int kk = 0; kk < BK; kk++) {
            float a[8], bb2[4];
#pragma unroll
            for (int i = 0; i < 8; i++) a[i] = As[kk][ty * 8 + i];
#pragma unroll
            for (int j = 0; j < 4; j++) bb2[j] = Bs[kk][tx * 4 + j];
#pragma unroll
            for (int i = 0; i < 8; i++)
#pragma unroll
                for (int j = 0; j < 4; j++)
                    acc[i][j] = fmaf(a[i], bb2[j], acc[i][j]);
        }
        __syncthreads();
    }

#pragma unroll
    for (int i = 0; i < 8; i++) {
        const int r = row0 + ty * 8 + i;
#pragma unroll
        for (int j = 0; j < 4; j++) {
            const int c   = col0 + tx * 4 + j;
            const float v = acc[i][j] + bias[c];
            const size_t idx = (size_t)r * DIMN + c;
            if (EPI == 0) C[idx] = v;
            else          C[idx] = C[idx] + 0.3f * v;
        }
    }
}

// ---------------- per-batch tail: colsum -> top6 -> attention -> softmax ->
// agg -> layernorm -> v,s GEMVs -> sigmoid score -------------------------
__global__ void __launch_bounds__(256) final_kernel(
    const float* __restrict__ alpha_all,  // (128, 32, 20)
    const float* __restrict__ att_mask,   // (128, 1, 32)
    const float* __restrict__ ln_g, const float* __restrict__ ln_b,
    const float* __restrict__ sv_w, const float* __restrict__ sv_b,
    const float* __restrict__ ss_w, const float* __restrict__ ss_b,
    const float* __restrict__ cl_w, const float* __restrict__ cl_b,
    float* __restrict__ out)              // (128, 6)
{
    const int b    = blockIdx.x;
    const int t    = threadIdx.x;
    const int warp = t >> 5;
    const int lane = t & 31;

    __shared__ float spt [NTOP][DIMN];
    __shared__ float sagg[NTOP][DIMN];
    __shared__ float sc  [NTOP][DIMN];
    __shared__ float adj [SEQ][NTOP];
    __shared__ float sums[20];
    __shared__ int   idxs[NTOP];
    __shared__ float smask[SEQ];

    if (t < SEQ) smask[t] = att_mask[b * SEQ + t];
    __syncthreads();

    if (t < 20) {
        float s = 0.f;
        for (int si = 0; si < SEQ; si++)
            s = fmaf(alpha_all[((size_t)b * SEQ + si) * 20 + t], smask[si], s);
        sums[t] = s;
    }
    __syncthreads();

    if (t == 0) {   // lax.top_k: descending values, first index on ties
        unsigned used = 0;
        for (int k = 0; k < NTOP; k++) {
            int best = 0; float bv = -3.4e38f;
            for (int p = 0; p < 20; p++)
                if (!((used >> p) & 1u) && sums[p] > bv) { bv = sums[p]; best = p; }
            used |= (1u << best);
            idxs[k] = best;
        }
    }
    __syncthreads();

    for (int i = t; i < NTOP * DIMN; i += 256) {
        const int k = i >> 9, d = i & 511;
        spt[k][d] = g_psl[((size_t)b * 20 + idxs[k]) * DIMN + d];
    }
    __syncthreads();

    // adj[s][k] = <att_out[b,s,:], psl_topk[k,:]> / sqrt(512), masked
    for (int pair = warp; pair < SEQ * NTOP; pair += 8) {
        const int s = pair / NTOP;
        const int k = pair - s * NTOP;
        const float* xr = g_X + ((size_t)b * SEQ + s) * DIMN;
        float acc = 0.f;
        for (int d = lane; d < DIMN; d += 32)
            acc = fmaf(xr[d], spt[k][d], acc);
#pragma unroll
        for (int o = 16; o > 0; o >>= 1)
            acc += __shfl_down_sync(0xffffffffu, acc, o);
        if (lane == 0) {
            const float v = acc * 0.04419417382415922f; // 1/sqrt(512)
            adj[s][k] = (smask[s] > 0.f) ? v : -9.0e15f;
        }
    }
    __syncthreads();

    // softmax over s (axis=1) per k — one warp per k (SEQ == 32 lanes)
    if (warp < NTOP) {
        const int k = warp;
        float v = adj[lane][k];
        float m = v;
#pragma unroll
        for (int o = 16; o > 0; o >>= 1)
            m = fmaxf(m, __shfl_xor_sync(0xffffffffu, m, o));
        const float e = expf(v - m);
        float ss = e;
#pragma unroll
        for (int o = 16; o > 0; o >>= 1)
            ss += __shfl_xor_sync(0xffffffffu, ss, o);
        adj[lane][k] = e / ss;
    }
    __syncthreads();

    // psl_agg[k][d] = sum_s att_out[b,s,d] * adj[s][k]
    for (int d = t; d < DIMN; d += 256) {
        float a[NTOP];
#pragma unroll
        for (int k = 0; k < NTOP; k++) a[k] = 0.f;
        for (int s = 0; s < SEQ; s++) {
            const float xv = g_X[((size_t)b * SEQ + s) * DIMN + d];
#pragma unroll
            for (int k = 0; k < NTOP; k++) a[k] = fmaf(xv, adj[s][k], a[k]);
        }
#pragma unroll
        for (int k = 0; k < NTOP; k++) sagg[k][d] = a[k];
    }
    __syncthreads();

    // layernorm over d per k — warp per k
    if (warp < NTOP) {
        const int k = warp;
        float sum = 0.f, sq = 0.f;
        for (int d = lane; d < DIMN; d += 32) {
            const float v = sagg[k][d];
            sum += v;
            sq = fmaf(v, v, sq);
        }
#pragma unroll
        for (int o = 16; o > 0; o >>= 1) {
            sum += __shfl_xor_sync(0xffffffffu, sum, o);
            sq  += __shfl_xor_sync(0xffffffffu, sq,  o);
        }
        const float mu  = sum * (1.f / DIMN);
        const float var = sq * (1.f / DIMN) - mu * mu;
        const float inv = rsqrtf(var + 1e-5f);
        for (int d = lane; d < DIMN; d += 32)
            sagg[k][d] = (sagg[k][d] - mu) * inv * ln_g[d] + ln_b[d];
    }
    __syncthreads();

    // v = tanh(spt @ sv_w^T + sv_b), s = tanh(sagg @ ss_w^T + ss_b)
    // sc[k][d] = v*s*cl_w[d]
    for (int idx = t; idx < NTOP * DIMN; idx += 256) {
        const int k = idx >> 9, d = idx & 511;
        float accv = sv_b[d], accs = ss_b[d];
        const float4* wv = (const float4*)(sv_w + (size_t)d * DIMN);
        const float4* ws = (const float4*)(ss_w + (size_t)d * DIMN);
        const float4* pv = (const float4*)(&spt[k][0]);
        const float4* pa = (const float4*)(&sagg[k][0]);
#pragma unroll 4
        for (int e = 0; e < DIMN / 4; e++) {
            const float4 a = pv[e], w = wv[e];
            accv = fmaf(a.x, w.x, fmaf(a.y, w.y, fmaf(a.z, w.z, fmaf(a.w, w.w, accv))));
            const float4 a2 = pa[e], w2 = ws[e];
            accs = fmaf(a2.x, w2.x, fmaf(a2.y, w2.y, fmaf(a2.z, w2.z, fmaf(a2.w, w2.w, accs))));
        }
        sc[k][d] = tanhf(accv) * tanhf(accs) * cl_w[d];
    }
    __syncthreads();

    // score[k] = sigmoid(sum_d sc[k][d] + cl_b)  (deterministic warp reduce)
    if (warp < NTOP) {
        const int k = warp;
        float s = 0.f;
        for (int d = lane; d < DIMN; d += 32) s += sc[k][d];
#pragma unroll
        for (int o = 16; o > 0; o >>= 1)
            s += __shfl_xor_sync(0xffffffffu, s, o);
        if (lane == 0) {
            const float z = s + cl_b[0];
            out[b * NTOP + k] = 1.f / (1.f + expf(-z));
        }
    }
}

// ---------------- launch --------------------------------------------------
extern "C" void kernel_launch(void* const* d_in, const int* in_sizes, int n_in,
                              void* d_out, int out_size)
{
    const float* inputs   = (const float*)d_in[0];
    // d_in[1] = pos_tags (unused by the reference)
    const float* obj      = (const float*)d_in[2];
    const float* motion   = (const float*)d_in[3];
    const float* att_mask = (const float*)d_in[4];
    const float* alpha    = (const float*)d_in[5];
    const float* conv_w   = (const float*)d_in[6];
    const float* conv_b   = (const float*)d_in[7];
    const float* res_w1   = (const float*)d_in[8];
    const float* res_b1   = (const float*)d_in[9];
    const float* res_w2   = (const float*)d_in[10];
    const float* res_b2   = (const float*)d_in[11];
    const float* psl_w    = (const float*)d_in[12];
    const float* psl_b    = (const float*)d_in[13];
    const float* ln_g     = (const float*)d_in[14];
    const float* ln_b     = (const float*)d_in[15];
    const float* sv_w     = (const float*)d_in[16];
    const float* sv_b     = (const float*)d_in[17];
    const float* ss_w     = (const float*)d_in[18];
    const float* ss_b     = (const float*)d_in[19];
    const float* cl_w     = (const float*)d_in[20];
    const float* cl_b     = (const float*)d_in[21];
    float* out = (float*)d_out;

    float *X, *Y1, *PSL;
    cudaGetSymbolAddress((void**)&X,   g_X);
    cudaGetSymbolAddress((void**)&Y1,  g_Y1);
    cudaGetSymbolAddress((void**)&PSL, g_psl);

    const dim3 blk(256);
    const dim3 g1(DIMN / BN, (BS_ * SEQ) / BM);     // (8, 32)
    const dim3 g2(DIMN / BN, (BS_ * 2 * P_) / BM);  // (8, 20)

    // x = inputs @ conv_w^T + conv_b          (M=4096, K=10000)
    gemm_kernel<0, 0><<<g1, blk>>>(inputs, nullptr, conv_w, conv_b, X,
                                   BS_ * SEQ, 10000, 10000);
    // y1 = conv1d(relu(x), res_w1) + res_b1   (im2col, K=2560)
    gemm_kernel<1, 0><<<g1, blk>>>(X, nullptr, res_w1, res_b1, Y1,
                                   BS_ * SEQ, 2560, 0);
    // x += 0.3 * (conv1d(relu(y1), res_w2) + res_b2)
    gemm_kernel<1, 1><<<g1, blk>>>(Y1, nullptr, res_w2, res_b2, X,
                                   BS_ * SEQ, 2560, 0);
    // psl_all = concat(obj, motion) @ psl_w^T + psl_b   (M=2560, K=1024)
    gemm_kernel<2, 0><<<g2, blk>>>(obj, motion, psl_w, psl_b, PSL,
                                   BS_ * 2 * P_, 1024, 0);
    // tail
    final_kernel<<<BS_, blk>>>(alpha, att_mask, ln_g, ln_b,
                               sv_w, sv_b, ss_w, ss_b, cl_w, cl_b, out);
}

// round 3
// speedup vs baseline: 2.2631x; 2.2631x over previous
#include <cuda_runtime.h>
#include <cuda_bf16.h>
#include <math.h>
#include <stdint.h>

#define BS_    128
#define SEQ    32
#define DIMN   512
#define P_     10
#define NTOP   6

#define KBIG   10000
#define KBIGP  10016            // padded to multiple of 32
#define KCONV  2560             // 512*5
#define KPSL   1024

// ---------------- device scratch (no allocations allowed) -------------------
__device__ float g_X  [BS_ * SEQ * DIMN];
__device__ float g_Y1 [BS_ * SEQ * DIMN];
__device__ float g_psl[BS_ * 2 * P_ * DIMN];

__device__ __nv_bfloat16 g_AH [(size_t)4096 * KBIGP];
__device__ __nv_bfloat16 g_AL [(size_t)4096 * KBIGP];
__device__ __nv_bfloat16 g_WcH[(size_t)512 * KBIGP];
__device__ __nv_bfloat16 g_WcL[(size_t)512 * KBIGP];
__device__ __nv_bfloat16 g_W1H[512 * KCONV], g_W1L[512 * KCONV];
__device__ __nv_bfloat16 g_W2H[512 * KCONV], g_W2L[512 * KCONV];
__device__ __nv_bfloat16 g_WpH[512 * KPSL],  g_WpL[512 * KPSL];

// ---------------- ptx helpers -------------------------------------------------
__device__ __forceinline__ uint32_t smem_u32(const void* p) {
    uint32_t a;
    asm("{ .reg .u64 t; cvta.to.shared.u64 t, %1; cvt.u32.u64 %0, t; }" : "=r"(a) : "l"(p));
    return a;
}
__device__ __forceinline__ void cp16(uint32_t sa, const void* g) {
    asm volatile("cp.async.cg.shared.global [%0], [%1], 16;\n" :: "r"(sa), "l"(g) : "memory");
}
__device__ __forceinline__ void cp_commit() {
    asm volatile("cp.async.commit_group;\n" ::: "memory");
}
template<int N> __device__ __forceinline__ void cp_wait() {
    asm volatile("cp.async.wait_group %0;\n" :: "n"(N) : "memory");
}
__device__ __forceinline__ void mma_bf16(float* d,
    uint32_t a0, uint32_t a1, uint32_t a2, uint32_t a3,
    uint32_t b0, uint32_t b1)
{
    asm volatile(
        "mma.sync.aligned.m16n8k16.row.col.f32.bf16.bf16.f32 "
        "{%0,%1,%2,%3}, {%4,%5,%6,%7}, {%8,%9}, {%0,%1,%2,%3};"
        : "+f"(d[0]), "+f"(d[1]), "+f"(d[2]), "+f"(d[3])
        : "r"(a0), "r"(a1), "r"(a2), "r"(a3), "r"(b0), "r"(b1));
}

// ---------------- conversion kernels -----------------------------------------
__global__ void split_hilo(const float* __restrict__ src,
                           __nv_bfloat16* __restrict__ hi,
                           __nv_bfloat16* __restrict__ lo,
                           int K, int Kpad, long n)
{
    long idx = (long)blockIdx.x * blockDim.x + threadIdx.x;
    if (idx >= n) return;
    int row = (int)(idx / Kpad);
    int col = (int)(idx - (long)row * Kpad);
    float v = (col < K) ? src[(size_t)row * K + col] : 0.f;
    __nv_bfloat16 h = __float2bfloat16(v);
    hi[idx] = h;
    lo[idx] = __float2bfloat16(v - __bfloat162float(h));
}

// im2col (conv1d k=5 pad=2) of relu(X), X layout (b, s, din) -> (4096, 2560)
__global__ void im2col_hilo(const float* __restrict__ X,
                            __nv_bfloat16* __restrict__ hi,
                            __nv_bfloat16* __restrict__ lo)
{
    long idx = (long)blockIdx.x * blockDim.x + threadIdx.x;
    const long n = (long)4096 * KCONV;
    if (idx >= n) return;
    int row = (int)(idx / KCONV);
    int k   = (int)(idx - (long)row * KCONV);
    int din = k / 5, tap = k - din * 5;
    int b = row >> 5, s = row & 31;
    int s2 = s + tap - 2;
    float v = 0.f;
    if (s2 >= 0 && s2 < SEQ) {
        v = X[((size_t)(b * SEQ + s2)) * DIMN + din];
        v = v > 0.f ? v : 0.f;
    }
    __nv_bfloat16 h = __float2bfloat16(v);
    hi[idx] = h;
    lo[idx] = __float2bfloat16(v - __bfloat162float(h));
}

// concat(obj, motion) rows -> (2560, 1024)
__global__ void concat_hilo(const float* __restrict__ obj,
                            const float* __restrict__ motion,
                            __nv_bfloat16* __restrict__ hi,
                            __nv_bfloat16* __restrict__ lo)
{
    long idx = (long)blockIdx.x * blockDim.x + threadIdx.x;
    const long n = (long)2560 * KPSL;
    if (idx >= n) return;
    int row = (int)(idx >> 10);
    int col = (int)(idx & 1023);
    int b = row / 20, p = row - b * 20;
    float v = (p < P_) ? obj   [((size_t)(b * P_ + p      )) * 1024 + col]
                       : motion[((size_t)(b * P_ + p - P_ )) * 1024 + col];
    __nv_bfloat16 h = __float2bfloat16(v);
    hi[idx] = h;
    lo[idx] = __float2bfloat16(v - __bfloat162float(h));
}

// ---------------- mma.sync GEMM ------------------------------------------------
// C[M x 512] = (AH+AL)[M x Kpad] * (BH+BL)[512 x Kpad]^T + bias  (3-pass split)
// CTA tile 128(M) x 128(N), BK=32, 256 threads = 8 warps (2 M x 4 N),
// warp tile 64 x 32, double-buffered cp.async.
// smem per matrix tile: 128 rows x pitch 40 bf16 (80 B) -> 10240 B
#define PITCH32 20          // u32 per row
#define MATB    10240u      // bytes per matrix tile
#define STAGEB  (4u * MATB) // AH, AL, BH, BL

__device__ __forceinline__ void load_stage(
    uint32_t sb, int t,
    const __nv_bfloat16* __restrict__ AH, const __nv_bfloat16* __restrict__ AL,
    const __nv_bfloat16* __restrict__ BH, const __nv_bfloat16* __restrict__ BL,
    int row0, int col0, int Kpad, int k0)
{
    const __nv_bfloat16* src[4] = {AH, AL, BH, BL};
#pragma unroll
    for (int m = 0; m < 4; m++) {
        const int rb = (m < 2) ? row0 : col0;
        const uint32_t tb = sb + (uint32_t)m * MATB;
        const __nv_bfloat16* s = src[m];
#pragma unroll
        for (int j = 0; j < 2; j++) {
            const int cid = j * 256 + t;       // 512 chunks: row = cid/4, ch = cid%4
            const int r  = cid >> 2, ch = cid & 3;
            cp16(tb + (uint32_t)(r * 80 + ch * 16),
                 s + (size_t)(rb + r) * Kpad + k0 + ch * 8);
        }
    }
}

template<int EPI>
__global__ void __launch_bounds__(256) gemm_mma(
    const __nv_bfloat16* __restrict__ AH, const __nv_bfloat16* __restrict__ AL,
    const __nv_bfloat16* __restrict__ BH, const __nv_bfloat16* __restrict__ BL,
    const float* __restrict__ bias, float* __restrict__ C, int Kpad)
{
    extern __shared__ char smem[];
    const uint32_t sbase = smem_u32(smem);
    const int t = threadIdx.x;
    const int wid = t >> 5, lane = t & 31;
    const int warp_m = wid >> 2, warp_n = wid & 3;
    const int tr = lane >> 2, tc = lane & 3;
    const int row0 = blockIdx.y * 128;
    const int col0 = blockIdx.x * 128;

    float acc[4][4][4];
#pragma unroll
    for (int i = 0; i < 4; i++)
#pragma unroll
        for (int j = 0; j < 4; j++)
#pragma unroll
            for (int e = 0; e < 4; e++) acc[i][j][e] = 0.f;

    const int nch = Kpad >> 5;

    load_stage(sbase, t, AH, AL, BH, BL, row0, col0, Kpad, 0);
    cp_commit();

    for (int i = 0; i < nch; i++) {
        const int cur = i & 1;
        if (i + 1 < nch) {
            load_stage(sbase + (cur ^ 1) * STAGEB, t, AH, AL, BH, BL,
                       row0, col0, Kpad, (i + 1) * 32);
            cp_commit();
            cp_wait<1>();
        } else {
            cp_wait<0>();
        }
        __syncthreads();

        const uint32_t* S = (const uint32_t*)(smem + cur * STAGEB);
        const uint32_t* mats[4] = {S, S + MATB / 4, S + 2 * (MATB / 4), S + 3 * (MATB / 4)};
#pragma unroll
        for (int split = 0; split < 3; split++) {
            const uint32_t* pA = mats[split == 1 ? 1 : 0];
            const uint32_t* pB = mats[split == 2 ? 3 : 2];
#pragma unroll
            for (int k16 = 0; k16 < 2; k16++) {
                const int c = k16 * 8 + tc;
                uint32_t b0[4], b1[4];
#pragma unroll
                for (int nt = 0; nt < 4; nt++) {
                    const int n = warp_n * 32 + nt * 8 + tr;
                    b0[nt] = pB[n * PITCH32 + c];
                    b1[nt] = pB[n * PITCH32 + c + 4];
                }
#pragma unroll
                for (int mt = 0; mt < 4; mt++) {
                    const int r = warp_m * 64 + mt * 16 + tr;
                    const uint32_t a0 = pA[r * PITCH32 + c];
                    const uint32_t a1 = pA[(r + 8) * PITCH32 + c];
                    const uint32_t a2 = pA[r * PITCH32 + c + 4];
                    const uint32_t a3 = pA[(r + 8) * PITCH32 + c + 4];
#pragma unroll
                    for (int nt = 0; nt < 4; nt++)
                        mma_bf16(acc[mt][nt], a0, a1, a2, a3, b0[nt], b1[nt]);
                }
            }
        }
        __syncthreads();
    }

    // epilogue
#pragma unroll
    for (int mt = 0; mt < 4; mt++) {
        const int r0 = row0 + warp_m * 64 + mt * 16 + tr;
#pragma unroll
        for (int nt = 0; nt < 4; nt++) {
            const int cc = col0 + warp_n * 32 + nt * 8 + tc * 2;
            const float bx = __ldg(bias + cc), by = __ldg(bias + cc + 1);
            float2 v0 = make_float2(acc[mt][nt][0] + bx, acc[mt][nt][1] + by);
            float2 v1 = make_float2(acc[mt][nt][2] + bx, acc[mt][nt][3] + by);
            float* p0 = C + (size_t)r0 * DIMN + cc;
            float* p1 = C + (size_t)(r0 + 8) * DIMN + cc;
            if (EPI == 1) {
                float2 o0 = *(const float2*)p0;
                float2 o1 = *(const float2*)p1;
                v0.x = o0.x + 0.3f * v0.x;  v0.y = o0.y + 0.3f * v0.y;
                v1.x = o1.x + 0.3f * v1.x;  v1.y = o1.y + 0.3f * v1.y;
            }
            *(float2*)p0 = v0;
            *(float2*)p1 = v1;
        }
    }
}

// ---------------- per-batch tail ------------------------------------------------
__global__ void __launch_bounds__(256) final_kernel(
    const float* __restrict__ alpha_all,  // (128, 32, 20)
    const float* __restrict__ att_mask,   // (128, 1, 32)
    const float* __restrict__ ln_g, const float* __restrict__ ln_b,
    const float* __restrict__ sv_w, const float* __restrict__ sv_b,
    const float* __restrict__ ss_w, const float* __restrict__ ss_b,
    const float* __restrict__ cl_w, const float* __restrict__ cl_b,
    float* __restrict__ out)              // (128, 6)
{
    const int b    = blockIdx.x;
    const int t    = threadIdx.x;
    const int warp = t >> 5;
    const int lane = t & 31;

    __shared__ float spt [NTOP][DIMN];
    __shared__ float sagg[NTOP][DIMN];
    __shared__ float sc  [NTOP][DIMN];
    __shared__ float adj [SEQ][NTOP];
    __shared__ float sums[20];
    __shared__ int   idxs[NTOP];
    __shared__ float smask[SEQ];

    if (t < SEQ) smask[t] = att_mask[b * SEQ + t];
    __syncthreads();

    if (t < 20) {
        float s = 0.f;
        for (int si = 0; si < SEQ; si++)
            s = fmaf(alpha_all[((size_t)b * SEQ + si) * 20 + t], smask[si], s);
        sums[t] = s;
    }
    __syncthreads();

    if (t == 0) {   // lax.top_k: descending values, first index on ties
        unsigned used = 0;
        for (int k = 0; k < NTOP; k++) {
            int best = 0; float bv = -3.4e38f;
            for (int p = 0; p < 20; p++)
                if (!((used >> p) & 1u) && sums[p] > bv) { bv = sums[p]; best = p; }
            used |= (1u << best);
            idxs[k] = best;
        }
    }
    __syncthreads();

    for (int i = t; i < NTOP * DIMN; i += 256) {
        const int k = i >> 9, d = i & 511;
        spt[k][d] = g_psl[((size_t)b * 20 + idxs[k]) * DIMN + d];
    }
    __syncthreads();

    for (int pair = warp; pair < SEQ * NTOP; pair += 8) {
        const int s = pair / NTOP;
        const int k = pair - s * NTOP;
        const float* xr = g_X + ((size_t)b * SEQ + s) * DIMN;
        float acc = 0.f;
        for (int d = lane; d < DIMN; d += 32)
            acc = fmaf(xr[d], spt[k][d], acc);
#pragma unroll
        for (int o = 16; o > 0; o >>= 1)
            acc += __shfl_down_sync(0xffffffffu, acc, o);
        if (lane == 0) {
            const float v = acc * 0.04419417382415922f;
            adj[s][k] = (smask[s] > 0.f) ? v : -9.0e15f;
        }
    }
    __syncthreads();

    if (warp < NTOP) {
        const int k = warp;
        float v = adj[lane][k];
        float m = v;
#pragma unroll
        for (int o = 16; o > 0; o >>= 1)
            m = fmaxf(m, __shfl_xor_sync(0xffffffffu, m, o));
        const float e = expf(v - m);
        float ss = e;
#pragma unroll
        for (int o = 16; o > 0; o >>= 1)
            ss += __shfl_xor_sync(0xffffffffu, ss, o);
        adj[lane][k] = e / ss;
    }
    __syncthreads();

    for (int d = t; d < DIMN; d += 256) {
        float a[NTOP];
#pragma unroll
        for (int k = 0; k < NTOP; k++) a[k] = 0.f;
        for (int s = 0; s < SEQ; s++) {
            const float xv = g_X[((size_t)b * SEQ + s) * DIMN + d];
#pragma unroll
            for (int k = 0; k < NTOP; k++) a[k] = fmaf(xv, adj[s][k], a[k]);
        }
#pragma unroll
        for (int k = 0; k < NTOP; k++) sagg[k][d] = a[k];
    }
    __syncthreads();

    if (warp < NTOP) {
        const int k = warp;
        float sum = 0.f, sq = 0.f;
        for (int d = lane; d < DIMN; d += 32) {
            const float v = sagg[k][d];
            sum += v;
            sq = fmaf(v, v, sq);
        }
#pragma unroll
        for (int o = 16; o > 0; o >>= 1) {
            sum += __shfl_xor_sync(0xffffffffu, sum, o);
            sq  += __shfl_xor_sync(0xffffffffu, sq,  o);
        }
        const float mu  = sum * (1.f / DIMN);
        const float var = sq * (1.f / DIMN) - mu * mu;
        const float inv = rsqrtf(var + 1e-5f);
        for (int d = lane; d < DIMN; d += 32)
            sagg[k][d] = (sagg[k][d] - mu) * inv * ln_g[d] + ln_b[d];
    }
    __syncthreads();

    for (int idx = t; idx < NTOP * DIMN; idx += 256) {
        const int k = idx >> 9, d = idx & 511;
        float accv = sv_b[d], accs = ss_b[d];
        const float4* wv = (const float4*)(sv_w + (size_t)d * DIMN);
        const float4* ws = (const float4*)(ss_w + (size_t)d * DIMN);
        const float4* pv = (const float4*)(&spt[k][0]);
        const float4* pa = (const float4*)(&sagg[k][0]);
#pragma unroll 4
        for (int e = 0; e < DIMN / 4; e++) {
            const float4 a = pv[e], w = wv[e];
            accv = fmaf(a.x, w.x, fmaf(a.y, w.y, fmaf(a.z, w.z, fmaf(a.w, w.w, accv))));
            const float4 a2 = pa[e], w2 = ws[e];
            accs = fmaf(a2.x, w2.x, fmaf(a2.y, w2.y, fmaf(a2.z, w2.z, fmaf(a2.w, w2.w, accs))));
        }
        sc[k][d] = tanhf(accv) * tanhf(accs) * cl_w[d];
    }
    __syncthreads();

    if (warp < NTOP) {
        const int k = warp;
        float s = 0.f;
        for (int d = lane; d < DIMN; d += 32) s += sc[k][d];
#pragma unroll
        for (int o = 16; o > 0; o >>= 1)
            s += __shfl_xor_sync(0xffffffffu, s, o);
        if (lane == 0) {
            const float z = s + cl_b[0];
            out[b * NTOP + k] = 1.f / (1.f + expf(-z));
        }
    }
}

// ---------------- launch ----------------------------------------------------------
extern "C" void kernel_launch(void* const* d_in, const int* in_sizes, int n_in,
                              void* d_out, int out_size)
{
    const float* inputs   = (const float*)d_in[0];
    const float* obj      = (const float*)d_in[2];
    const float* motion   = (const float*)d_in[3];
    const float* att_mask = (const float*)d_in[4];
    const float* alpha    = (const float*)d_in[5];
    const float* conv_w   = (const float*)d_in[6];
    const float* conv_b   = (const float*)d_in[7];
    const float* res_w1   = (const float*)d_in[8];
    const float* res_b1   = (const float*)d_in[9];
    const float* res_w2   = (const float*)d_in[10];
    const float* res_b2   = (const float*)d_in[11];
    const float* psl_w    = (const float*)d_in[12];
    const float* psl_b    = (const float*)d_in[13];
    const float* ln_g     = (const float*)d_in[14];
    const float* ln_b     = (const float*)d_in[15];
    const float* sv_w     = (const float*)d_in[16];
    const float* sv_b     = (const float*)d_in[17];
    const float* ss_w     = (const float*)d_in[18];
    const float* ss_b     = (const float*)d_in[19];
    const float* cl_w     = (const float*)d_in[20];
    const float* cl_b     = (const float*)d_in[21];
    float* out = (float*)d_out;

    float *X, *Y1, *PSL;
    __nv_bfloat16 *AH, *AL, *WcH, *WcL, *W1H, *W1L, *W2H, *W2L, *WpH, *WpL;
    cudaGetSymbolAddress((void**)&X,   g_X);
    cudaGetSymbolAddress((void**)&Y1,  g_Y1);
    cudaGetSymbolAddress((void**)&PSL, g_psl);
    cudaGetSymbolAddress((void**)&AH,  g_AH);
    cudaGetSymbolAddress((void**)&AL,  g_AL);
    cudaGetSymbolAddress((void**)&WcH, g_WcH);
    cudaGetSymbolAddress((void**)&WcL, g_WcL);
    cudaGetSymbolAddress((void**)&W1H, g_W1H);
    cudaGetSymbolAddress((void**)&W1L, g_W1L);
    cudaGetSymbolAddress((void**)&W2H, g_W2H);
    cudaGetSymbolAddress((void**)&W2L, g_W2L);
    cudaGetSymbolAddress((void**)&WpH, g_WpH);
    cudaGetSymbolAddress((void**)&WpL, g_WpL);

    const int SMEM_BYTES = 2 * 4 * 10240;   // 81920
    cudaFuncSetAttribute(gemm_mma<0>, cudaFuncAttributeMaxDynamicSharedMemorySize, SMEM_BYTES);
    cudaFuncSetAttribute(gemm_mma<1>, cudaFuncAttributeMaxDynamicSharedMemorySize, SMEM_BYTES);

    const dim3 blk(256);
    const dim3 gBig(4, 32);     // N=512/128, M=4096/128
    const dim3 gPsl(4, 20);     // M=2560/128

    // weight conversions
    {
        long n = (long)512 * KBIGP;
        split_hilo<<<(unsigned)((n + 255) / 256), 256>>>(conv_w, WcH, WcL, KBIG, KBIGP, n);
        n = (long)512 * KCONV;
        split_hilo<<<(unsigned)((n + 255) / 256), 256>>>(res_w1, W1H, W1L, KCONV, KCONV, n);
        split_hilo<<<(unsigned)((n + 255) / 256), 256>>>(res_w2, W2H, W2L, KCONV, KCONV, n);
        n = (long)512 * KPSL;
        split_hilo<<<(unsigned)((n + 255) / 256), 256>>>(psl_w, WpH, WpL, KPSL, KPSL, n);
    }
    // inputs -> hi/lo (padded)
    {
        long n = (long)4096 * KBIGP;
        split_hilo<<<(unsigned)((n + 255) / 256), 256>>>(inputs, AH, AL, KBIG, KBIGP, n);
    }
    // GEMM1: x = inputs @ conv_w^T + conv_b
    gemm_mma<0><<<gBig, blk, SMEM_BYTES>>>(AH, AL, WcH, WcL, conv_b, X, KBIGP);

    // im2col(relu(x)) -> A
    {
        long n = (long)4096 * KCONV;
        im2col_hilo<<<(unsigned)((n + 255) / 256), 256>>>(X, AH, AL);
    }
    // GEMM2: y1 = conv1 + b1
    gemm_mma<0><<<gBig, blk, SMEM_BYTES>>>(AH, AL, W1H, W1L, res_b1, Y1, KCONV);

    // im2col(relu(y1)) -> A
    {
        long n = (long)4096 * KCONV;
        im2col_hilo<<<(unsigned)((n + 255) / 256), 256>>>(Y1, AH, AL);
    }
    // GEMM3: x += 0.3 * (conv2 + b2)
    gemm_mma<1><<<gBig, blk, SMEM_BYTES>>>(AH, AL, W2H, W2L, res_b2, X, KCONV);

    // concat proposals -> A
    {
        long n = (long)2560 * KPSL;
        concat_hilo<<<(unsigned)((n + 255) / 256), 256>>>(obj, motion, AH, AL);
    }
    // GEMM4: psl_all
    gemm_mma<0><<<gPsl, blk, SMEM_BYTES>>>(AH, AL, WpH, WpL, psl_b, PSL, KPSL);

    // tail
    final_kernel<<<BS_, 256>>>(alpha, att_mask, ln_g, ln_b,
                               sv_w, sv_b, ss_w, ss_b, cl_w, cl_b, out);
}

// round 4
// speedup vs baseline: 3.7728x; 1.6671x over previous
#include <cuda_runtime.h>
#include <cuda_fp16.h>
#include <math.h>
#include <stdint.h>

#define BS_    128
#define SEQ    32
#define DIMN   512
#define P_     10
#define NTOP   6

#define KBIG   10000
#define KBIGP  10016            // padded to multiple of 32
#define KCONV  2560             // 512*5
#define KPSL   1024

// ---------------- device scratch (no allocations allowed) -------------------
__device__ float g_X  [BS_ * SEQ * DIMN];
__device__ float g_Y1 [BS_ * SEQ * DIMN];
__device__ float g_psl[BS_ * 2 * P_ * DIMN];

__device__ __half g_A  [(size_t)4096 * KBIGP];   // activations (reused per GEMM)
__device__ __half g_Wc [(size_t)512 * KBIGP];
__device__ __half g_W1 [512 * KCONV];
__device__ __half g_W2 [512 * KCONV];
__device__ __half g_Wp [512 * KPSL];

// ---------------- ptx helpers -------------------------------------------------
__device__ __forceinline__ void cp16(uint32_t sa, const void* g) {
    asm volatile("cp.async.cg.shared.global [%0], [%1], 16;\n" :: "r"(sa), "l"(g) : "memory");
}
__device__ __forceinline__ void cp_commit() {
    asm volatile("cp.async.commit_group;\n" ::: "memory");
}
template<int N> __device__ __forceinline__ void cp_wait() {
    asm volatile("cp.async.wait_group %0;\n" :: "n"(N) : "memory");
}
__device__ __forceinline__ uint32_t smem_u32(const void* p) {
    uint32_t a;
    asm("{ .reg .u64 t; cvta.to.shared.u64 t, %1; cvt.u32.u64 %0, t; }" : "=r"(a) : "l"(p));
    return a;
}
__device__ __forceinline__ void mma_f16(float* d,
    uint32_t a0, uint32_t a1, uint32_t a2, uint32_t a3,
    uint32_t b0, uint32_t b1)
{
    asm volatile(
        "mma.sync.aligned.m16n8k16.row.col.f32.f16.f16.f32 "
        "{%0,%1,%2,%3}, {%4,%5,%6,%7}, {%8,%9}, {%0,%1,%2,%3};"
        : "+f"(d[0]), "+f"(d[1]), "+f"(d[2]), "+f"(d[3])
        : "r"(a0), "r"(a1), "r"(a2), "r"(a3), "r"(b0), "r"(b1));
}

// ---------------- conversion kernels (vectorized x8, 32-bit indexing) ---------
// fp32 (rows x K) -> fp16 (rows x Kpad), zero pad
__global__ void __launch_bounds__(256) f32_to_f16_pad(
    const float* __restrict__ src, __half* __restrict__ dst,
    int K, int Kpad, int total_chunks, int chunksPerRow)
{
    int i = blockIdx.x * blockDim.x + threadIdx.x;
    if (i >= total_chunks) return;
    int row = i / chunksPerRow;
    int c8  = (i - row * chunksPerRow) << 3;
    const float* s = src + (size_t)row * K + c8;
    __half h[8];
    if (c8 + 8 <= K) {
        const float4 v0 = *(const float4*)s;
        const float4 v1 = *(const float4*)(s + 4);
        h[0] = __float2half(v0.x); h[1] = __float2half(v0.y);
        h[2] = __float2half(v0.z); h[3] = __float2half(v0.w);
        h[4] = __float2half(v1.x); h[5] = __float2half(v1.y);
        h[6] = __float2half(v1.z); h[7] = __float2half(v1.w);
    } else {
#pragma unroll
        for (int j = 0; j < 8; j++)
            h[j] = (c8 + j < K) ? __float2half(s[j]) : __float2half(0.f);
    }
    *(uint4*)(dst + (size_t)row * Kpad + c8) = *(const uint4*)h;
}

// res_w (512, 512, 5) -> fp16 (512, 2560) with k = tap*512 + din
__global__ void __launch_bounds__(256) reorder_w_f16(
    const float* __restrict__ src, __half* __restrict__ dst)
{
    int i = blockIdx.x * blockDim.x + threadIdx.x;
    if (i >= 512 * KCONV) return;
    int dout = i / KCONV;
    int k    = i - dout * KCONV;
    int tap  = k >> 9;           // k / 512
    int din  = k & 511;
    dst[i] = __float2half(src[dout * KCONV + din * 5 + tap]);
}

// im2col of relu(X): A(row, tap*512+din) = relu(X[b, s+tap-2, din]); vector x8
__global__ void __launch_bounds__(256) im2col_f16(
    const float* __restrict__ X, __half* __restrict__ A)
{
    int i = blockIdx.x * blockDim.x + threadIdx.x;      // 4096*5*64
    if (i >= 4096 * 5 * 64) return;
    int row = i / 320;
    int rem = i - row * 320;
    int tap = rem >> 6;
    int d8  = (rem & 63) << 3;
    int b = row >> 5, s = row & 31;
    int s2 = s + tap - 2;
    __half h[8];
    if (s2 >= 0 && s2 < SEQ) {
        const float* xp = X + ((size_t)(b * SEQ + s2)) * DIMN + d8;
        const float4 v0 = *(const float4*)xp;
        const float4 v1 = *(const float4*)(xp + 4);
        h[0] = __float2half(fmaxf(v0.x, 0.f)); h[1] = __float2half(fmaxf(v0.y, 0.f));
        h[2] = __float2half(fmaxf(v0.z, 0.f)); h[3] = __float2half(fmaxf(v0.w, 0.f));
        h[4] = __float2half(fmaxf(v1.x, 0.f)); h[5] = __float2half(fmaxf(v1.y, 0.f));
        h[6] = __float2half(fmaxf(v1.z, 0.f)); h[7] = __float2half(fmaxf(v1.w, 0.f));
    } else {
#pragma unroll
        for (int j = 0; j < 8; j++) h[j] = __float2half(0.f);
    }
    *(uint4*)(A + (size_t)row * KCONV + tap * 512 + d8) = *(const uint4*)h;
}

// concat(obj, motion) -> fp16 (2560, 1024); vector x8
__global__ void __launch_bounds__(256) concat_f16(
    const float* __restrict__ obj, const float* __restrict__ motion,
    __half* __restrict__ A)
{
    int i = blockIdx.x * blockDim.x + threadIdx.x;      // 2560*128
    if (i >= 2560 * 128) return;
    int row = i >> 7;
    int c8  = (i & 127) << 3;
    int b = row / 20, p = row - b * 20;
    const float* s = (p < P_) ? obj    + ((size_t)(b * P_ + p      )) * 1024 + c8
                              : motion + ((size_t)(b * P_ + p - P_ )) * 1024 + c8;
    const float4 v0 = *(const float4*)s;
    const float4 v1 = *(const float4*)(s + 4);
    __half h[8];
    h[0] = __float2half(v0.x); h[1] = __float2half(v0.y);
    h[2] = __float2half(v0.z); h[3] = __float2half(v0.w);
    h[4] = __float2half(v1.x); h[5] = __float2half(v1.y);
    h[6] = __float2half(v1.z); h[7] = __float2half(v1.w);
    *(uint4*)(A + (size_t)row * KPSL + c8) = *(const uint4*)h;
}

// ---------------- mma.sync GEMM (single pass fp16) ---------------------------
// C[M x 512] = A[M x Kpad] * B[512 x Kpad]^T + bias
// CTA tile 128 x 128, BK=32, 256 threads (2x4 warps, warp tile 64x32),
// double-buffered cp.async. smem tile: 128 rows x pitch 40 half (80 B).
#define PITCH32 20          // u32 per row
#define MATB    10240u      // bytes per matrix tile
#define STAGEB  (2u * MATB) // A, B

__device__ __forceinline__ void load_stage(
    uint32_t sb, int t,
    const __half* __restrict__ A, const __half* __restrict__ B,
    int row0, int col0, int Kpad, int k0)
{
    const __half* src[2] = {A, B};
#pragma unroll
    for (int m = 0; m < 2; m++) {
        const int rb = (m == 0) ? row0 : col0;
        const uint32_t tb = sb + (uint32_t)m * MATB;
        const __half* s = src[m];
#pragma unroll
        for (int j = 0; j < 2; j++) {
            const int cid = j * 256 + t;       // 512 chunks: row = cid/4, ch = cid%4
            const int r  = cid >> 2, ch = cid & 3;
            cp16(tb + (uint32_t)(r * 80 + ch * 16),
                 s + (size_t)(rb + r) * Kpad + k0 + ch * 8);
        }
    }
}

template<int EPI>
__global__ void __launch_bounds__(256) gemm_mma(
    const __half* __restrict__ A, const __half* __restrict__ B,
    const float* __restrict__ bias, float* __restrict__ C, int Kpad)
{
    extern __shared__ char smem[];
    const uint32_t sbase = smem_u32(smem);
    const int t = threadIdx.x;
    const int wid = t >> 5, lane = t & 31;
    const int warp_m = wid >> 2, warp_n = wid & 3;
    const int tr = lane >> 2, tc = lane & 3;
    const int row0 = blockIdx.y * 128;
    const int col0 = blockIdx.x * 128;

    float acc[4][4][4];
#pragma unroll
    for (int i = 0; i < 4; i++)
#pragma unroll
        for (int j = 0; j < 4; j++)
#pragma unroll
            for (int e = 0; e < 4; e++) acc[i][j][e] = 0.f;

    const int nch = Kpad >> 5;

    load_stage(sbase, t, A, B, row0, col0, Kpad, 0);
    cp_commit();

    for (int i = 0; i < nch; i++) {
        const int cur = i & 1;
        if (i + 1 < nch) {
            load_stage(sbase + (cur ^ 1) * STAGEB, t, A, B,
                       row0, col0, Kpad, (i + 1) * 32);
            cp_commit();
            cp_wait<1>();
        } else {
            cp_wait<0>();
        }
        __syncthreads();

        const uint32_t* S  = (const uint32_t*)(smem + cur * STAGEB);
        const uint32_t* pA = S;
        const uint32_t* pB = S + MATB / 4;
#pragma unroll
        for (int k16 = 0; k16 < 2; k16++) {
            const int c = k16 * 8 + tc;
            uint32_t b0[4], b1[4];
#pragma unroll
            for (int nt = 0; nt < 4; nt++) {
                const int n = warp_n * 32 + nt * 8 + tr;
                b0[nt] = pB[n * PITCH32 + c];
                b1[nt] = pB[n * PITCH32 + c + 4];
            }
#pragma unroll
            for (int mt = 0; mt < 4; mt++) {
                const int r = warp_m * 64 + mt * 16 + tr;
                const uint32_t a0 = pA[r * PITCH32 + c];
                const uint32_t a1 = pA[(r + 8) * PITCH32 + c];
                const uint32_t a2 = pA[r * PITCH32 + c + 4];
                const uint32_t a3 = pA[(r + 8) * PITCH32 + c + 4];
#pragma unroll
                for (int nt = 0; nt < 4; nt++)
                    mma_f16(acc[mt][nt], a0, a1, a2, a3, b0[nt], b1[nt]);
            }
        }
        __syncthreads();
    }

    // epilogue
#pragma unroll
    for (int mt = 0; mt < 4; mt++) {
        const int r0 = row0 + warp_m * 64 + mt * 16 + tr;
#pragma unroll
        for (int nt = 0; nt < 4; nt++) {
            const int cc = col0 + warp_n * 32 + nt * 8 + tc * 2;
            const float bx = __ldg(bias + cc), by = __ldg(bias + cc + 1);
            float2 v0 = make_float2(acc[mt][nt][0] + bx, acc[mt][nt][1] + by);
            float2 v1 = make_float2(acc[mt][nt][2] + bx, acc[mt][nt][3] + by);
            float* p0 = C + (size_t)r0 * DIMN + cc;
            float* p1 = C + (size_t)(r0 + 8) * DIMN + cc;
            if (EPI == 1) {
                float2 o0 = *(const float2*)p0;
                float2 o1 = *(const float2*)p1;
                v0.x = o0.x + 0.3f * v0.x;  v0.y = o0.y + 0.3f * v0.y;
                v1.x = o1.x + 0.3f * v1.x;  v1.y = o1.y + 0.3f * v1.y;
            }
            *(float2*)p0 = v0;
            *(float2*)p1 = v1;
        }
    }
}

// ---------------- per-batch tail ------------------------------------------------
__global__ void __launch_bounds__(256) final_kernel(
    const float* __restrict__ alpha_all,  // (128, 32, 20)
    const float* __restrict__ att_mask,   // (128, 1, 32)
    const float* __restrict__ ln_g, const float* __restrict__ ln_b,
    const float* __restrict__ sv_w, const float* __restrict__ sv_b,
    const float* __restrict__ ss_w, const float* __restrict__ ss_b,
    const float* __restrict__ cl_w, const float* __restrict__ cl_b,
    float* __restrict__ out)              // (128, 6)
{
    const int b    = blockIdx.x;
    const int t    = threadIdx.x;
    const int warp = t >> 5;
    const int lane = t & 31;

    __shared__ float spt [NTOP][DIMN];
    __shared__ float sagg[NTOP][DIMN];
    __shared__ float sc  [NTOP][DIMN];
    __shared__ float adj [SEQ][NTOP];
    __shared__ float sums[20];
    __shared__ int   idxs[NTOP];
    __shared__ float smask[SEQ];

    if (t < SEQ) smask[t] = att_mask[b * SEQ + t];
    __syncthreads();

    if (t < 20) {
        float s = 0.f;
        for (int si = 0; si < SEQ; si++)
            s = fmaf(alpha_all[((size_t)b * SEQ + si) * 20 + t], smask[si], s);
        sums[t] = s;
    }
    __syncthreads();

    if (t == 0) {   // lax.top_k: descending values, first index on ties
        unsigned used = 0;
        for (int k = 0; k < NTOP; k++) {
            int best = 0; float bv = -3.4e38f;
            for (int p = 0; p < 20; p++)
                if (!((used >> p) & 1u) && sums[p] > bv) { bv = sums[p]; best = p; }
            used |= (1u << best);
            idxs[k] = best;
        }
    }
    __syncthreads();

    for (int i = t; i < NTOP * DIMN; i += 256) {
        const int k = i >> 9, d = i & 511;
        spt[k][d] = g_psl[((size_t)b * 20 + idxs[k]) * DIMN + d];
    }
    __syncthreads();

    for (int pair = warp; pair < SEQ * NTOP; pair += 8) {
        const int s = pair / NTOP;
        const int k = pair - s * NTOP;
        const float* xr = g_X + ((size_t)b * SEQ + s) * DIMN;
        float acc = 0.f;
        for (int d = lane; d < DIMN; d += 32)
            acc = fmaf(xr[d], spt[k][d], acc);
#pragma unroll
        for (int o = 16; o > 0; o >>= 1)
            acc += __shfl_down_sync(0xffffffffu, acc, o);
        if (lane == 0) {
            const float v = acc * 0.04419417382415922f;
            adj[s][k] = (smask[s] > 0.f) ? v : -9.0e15f;
        }
    }
    __syncthreads();

    if (warp < NTOP) {
        const int k = warp;
        float v = adj[lane][k];
        float m = v;
#pragma unroll
        for (int o = 16; o > 0; o >>= 1)
            m = fmaxf(m, __shfl_xor_sync(0xffffffffu, m, o));
        const float e = expf(v - m);
        float ss = e;
#pragma unroll
        for (int o = 16; o > 0; o >>= 1)
            ss += __shfl_xor_sync(0xffffffffu, ss, o);
        adj[lane][k] = e / ss;
    }
    __syncthreads();

    for (int d = t; d < DIMN; d += 256) {
        float a[NTOP];
#pragma unroll
        for (int k = 0; k < NTOP; k++) a[k] = 0.f;
        for (int s = 0; s < SEQ; s++) {
            const float xv = g_X[((size_t)b * SEQ + s) * DIMN + d];
#pragma unroll
            for (int k = 0; k < NTOP; k++) a[k] = fmaf(xv, adj[s][k], a[k]);
        }
#pragma unroll
        for (int k = 0; k < NTOP; k++) sagg[k][d] = a[k];
    }
    __syncthreads();

    if (warp < NTOP) {
        const int k = warp;
        float sum = 0.f, sq = 0.f;
        for (int d = lane; d < DIMN; d += 32) {
            const float v = sagg[k][d];
            sum += v;
            sq = fmaf(v, v, sq);
        }
#pragma unroll
        for (int o = 16; o > 0; o >>= 1) {
            sum += __shfl_xor_sync(0xffffffffu, sum, o);
            sq  += __shfl_xor_sync(0xffffffffu, sq,  o);
        }
        const float mu  = sum * (1.f / DIMN);
        const float var = sq * (1.f / DIMN) - mu * mu;
        const float inv = rsqrtf(var + 1e-5f);
        for (int d = lane; d < DIMN; d += 32)
            sagg[k][d] = (sagg[k][d] - mu) * inv * ln_g[d] + ln_b[d];
    }
    __syncthreads();

    for (int idx = t; idx < NTOP * DIMN; idx += 256) {
        const int k = idx >> 9, d = idx & 511;
        float accv = sv_b[d], accs = ss_b[d];
        const float4* wv = (const float4*)(sv_w + (size_t)d * DIMN);
        const float4* ws = (const float4*)(ss_w + (size_t)d * DIMN);
        const float4* pv = (const float4*)(&spt[k][0]);
        const float4* pa = (const float4*)(&sagg[k][0]);
#pragma unroll 4
        for (int e = 0; e < DIMN / 4; e++) {
            const float4 a = pv[e], w = wv[e];
            accv = fmaf(a.x, w.x, fmaf(a.y, w.y, fmaf(a.z, w.z, fmaf(a.w, w.w, accv))));
            const float4 a2 = pa[e], w2 = ws[e];
            accs = fmaf(a2.x, w2.x, fmaf(a2.y, w2.y, fmaf(a2.z, w2.z, fmaf(a2.w, w2.w, accs))));
        }
        sc[k][d] = tanhf(accv) * tanhf(accs) * cl_w[d];
    }
    __syncthreads();

    if (warp < NTOP) {
        const int k = warp;
        float s = 0.f;
        for (int d = lane; d < DIMN; d += 32) s += sc[k][d];
#pragma unroll
        for (int o = 16; o > 0; o >>= 1)
            s += __shfl_xor_sync(0xffffffffu, s, o);
        if (lane == 0) {
            const float z = s + cl_b[0];
            out[b * NTOP + k] = 1.f / (1.f + expf(-z));
        }
    }
}

// ---------------- launch ----------------------------------------------------------
extern "C" void kernel_launch(void* const* d_in, const int* in_sizes, int n_in,
                              void* d_out, int out_size)
{
    const float* inputs   = (const float*)d_in[0];
    const float* obj      = (const float*)d_in[2];
    const float* motion   = (const float*)d_in[3];
    const float* att_mask = (const float*)d_in[4];
    const float* alpha    = (const float*)d_in[5];
    const float* conv_w   = (const float*)d_in[6];
    const float* conv_b   = (const float*)d_in[7];
    const float* res_w1   = (const float*)d_in[8];
    const float* res_b1   = (const float*)d_in[9];
    const float* res_w2   = (const float*)d_in[10];
    const float* res_b2   = (const float*)d_in[11];
    const float* psl_w    = (const float*)d_in[12];
    const float* psl_b    = (const float*)d_in[13];
    const float* ln_g     = (const float*)d_in[14];
    const float* ln_b     = (const float*)d_in[15];
    const float* sv_w     = (const float*)d_in[16];
    const float* sv_b     = (const float*)d_in[17];
    const float* ss_w     = (const float*)d_in[18];
    const float* ss_b     = (const float*)d_in[19];
    const float* cl_w     = (const float*)d_in[20];
    const float* cl_b     = (const float*)d_in[21];
    float* out = (float*)d_out;

    float *X, *Y1, *PSL;
    __half *A, *Wc, *W1, *W2, *Wp;
    cudaGetSymbolAddress((void**)&X,   g_X);
    cudaGetSymbolAddress((void**)&Y1,  g_Y1);
    cudaGetSymbolAddress((void**)&PSL, g_psl);
    cudaGetSymbolAddress((void**)&A,   g_A);
    cudaGetSymbolAddress((void**)&Wc,  g_Wc);
    cudaGetSymbolAddress((void**)&W1,  g_W1);
    cudaGetSymbolAddress((void**)&W2,  g_W2);
    cudaGetSymbolAddress((void**)&Wp,  g_Wp);

    const int SMEM_BYTES = 2 * (int)STAGEB;   // 40960
    cudaFuncSetAttribute(gemm_mma<0>, cudaFuncAttributeMaxDynamicSharedMemorySize, SMEM_BYTES);
    cudaFuncSetAttribute(gemm_mma<1>, cudaFuncAttributeMaxDynamicSharedMemorySize, SMEM_BYTES);

    const dim3 blk(256);
    const dim3 gBig(4, 32);     // N=512/128, M=4096/128
    const dim3 gPsl(4, 20);     // M=2560/128

    // conversions
    {
        const int cpr = KBIGP >> 3;                    // 1252
        int tc = 4096 * cpr;
        f32_to_f16_pad<<<(tc + 255) / 256, 256>>>(inputs, A, KBIG, KBIGP, tc, cpr);
        tc = 512 * cpr;
        f32_to_f16_pad<<<(tc + 255) / 256, 256>>>(conv_w, Wc, KBIG, KBIGP, tc, cpr);
        reorder_w_f16<<<(512 * KCONV + 255) / 256, 256>>>(res_w1, W1);
        reorder_w_f16<<<(512 * KCONV + 255) / 256, 256>>>(res_w2, W2);
        const int cprP = KPSL >> 3;
        tc = 512 * cprP;
        f32_to_f16_pad<<<(tc + 255) / 256, 256>>>(psl_w, Wp, KPSL, KPSL, tc, cprP);
    }

    // GEMM1: x = inputs @ conv_w^T + conv_b
    gemm_mma<0><<<gBig, blk, SMEM_BYTES>>>(A, Wc, conv_b, X, KBIGP);

    // im2col(relu(x)) -> A ; GEMM2
    im2col_f16<<<(4096 * 5 * 64 + 255) / 256, 256>>>(X, A);
    gemm_mma<0><<<gBig, blk, SMEM_BYTES>>>(A, W1, res_b1, Y1, KCONV);

    // im2col(relu(y1)) -> A ; GEMM3: x += 0.3*(...)
    im2col_f16<<<(4096 * 5 * 64 + 255) / 256, 256>>>(Y1, A);
    gemm_mma<1><<<gBig, blk, SMEM_BYTES>>>(A, W2, res_b2, X, KCONV);

    // concat proposals -> A ; GEMM4
    concat_f16<<<(2560 * 128 + 255) / 256, 256>>>(obj, motion, A);
    gemm_mma<0><<<gPsl, blk, SMEM_BYTES>>>(A, Wp, psl_b, PSL, KPSL);

    // tail
    final_kernel<<<BS_, 256>>>(alpha, att_mask, ln_g, ln_b,
                               sv_w, sv_b, ss_w, ss_b, cl_w, cl_b, out);
}

// round 5
// speedup vs baseline: 3.8121x; 1.0104x over previous
#include <cuda_runtime.h>
#include <cuda_fp16.h>
#include <math.h>
#include <stdint.h>

#define BS_    128
#define SEQ    32
#define DIMN   512
#define P_     10
#define NTOP   6

#define KBIG   10000
#define KBIGP  10016            // padded to multiple of 32
#define KCONV  2560             // 512*5 (tap-major: k = tap*512 + din)
#define KPSL   1024

// ---------------- device scratch (no allocations allowed) -------------------
__device__ float  g_X  [BS_ * SEQ * DIMN];          // x fp32 (residual + tail)
__device__ __half g_Xh [BS_ * SEQ * DIMN];          // fp16(relu(x))
__device__ __half g_Y1h[BS_ * SEQ * DIMN];          // fp16(relu(y1))
__device__ float  g_psl[BS_ * 2 * P_ * DIMN];

__device__ __half g_A  [(size_t)4096 * KBIGP];      // big activation buffer
__device__ __half g_Wc [(size_t)512 * KBIGP];
__device__ __half g_W1 [512 * KCONV];
__device__ __half g_W2 [512 * KCONV];
__device__ __half g_Wp [512 * KPSL];

// ---------------- ptx helpers -------------------------------------------------
__device__ __forceinline__ void cp16(uint32_t sa, const void* g) {
    asm volatile("cp.async.cg.shared.global [%0], [%1], 16;\n" :: "r"(sa), "l"(g) : "memory");
}
__device__ __forceinline__ void cp16z(uint32_t sa, const void* g, uint32_t srcsize) {
    asm volatile("cp.async.cg.shared.global [%0], [%1], 16, %2;\n"
                 :: "r"(sa), "l"(g), "r"(srcsize) : "memory");
}
__device__ __forceinline__ void cp_commit() {
    asm volatile("cp.async.commit_group;\n" ::: "memory");
}
template<int N> __device__ __forceinline__ void cp_wait() {
    asm volatile("cp.async.wait_group %0;\n" :: "n"(N) : "memory");
}
__device__ __forceinline__ uint32_t smem_u32(const void* p) {
    uint32_t a;
    asm("{ .reg .u64 t; cvta.to.shared.u64 t, %1; cvt.u32.u64 %0, t; }" : "=r"(a) : "l"(p));
    return a;
}
__device__ __forceinline__ void mma_f16(float* d,
    uint32_t a0, uint32_t a1, uint32_t a2, uint32_t a3,
    uint32_t b0, uint32_t b1)
{
    asm volatile(
        "mma.sync.aligned.m16n8k16.row.col.f32.f16.f16.f32 "
        "{%0,%1,%2,%3}, {%4,%5,%6,%7}, {%8,%9}, {%0,%1,%2,%3};"
        : "+f"(d[0]), "+f"(d[1]), "+f"(d[2]), "+f"(d[3])
        : "r"(a0), "r"(a1), "r"(a2), "r"(a3), "r"(b0), "r"(b1));
}

// ---------------- conversion kernels -------------------------------------------
// fp32 (rows x K) -> fp16 (rows x Kpad); 2D grid, vector x8
__global__ void __launch_bounds__(256) f32_to_f16_pad(
    const float* __restrict__ src, __half* __restrict__ dst, int K, int Kpad)
{
    const int row = blockIdx.y;
    const int c8  = (blockIdx.x * blockDim.x + threadIdx.x) << 3;
    if (c8 >= Kpad) return;
    const float* s = src + (size_t)row * K + c8;
    __half h[8];
    if (c8 + 8 <= K) {
        const float4 v0 = *(const float4*)s;
        const float4 v1 = *(const float4*)(s + 4);
        h[0] = __float2half(v0.x); h[1] = __float2half(v0.y);
        h[2] = __float2half(v0.z); h[3] = __float2half(v0.w);
        h[4] = __float2half(v1.x); h[5] = __float2half(v1.y);
        h[6] = __float2half(v1.z); h[7] = __float2half(v1.w);
    } else {
#pragma unroll
        for (int j = 0; j < 8; j++)
            h[j] = (c8 + j < K) ? __float2half(s[j]) : __float2half(0.f);
    }
    *(uint4*)(dst + (size_t)row * Kpad + c8) = *(const uint4*)h;
}

// res_w (512, 512, 5) -> fp16 (512, 2560) with k = tap*512 + din
__global__ void __launch_bounds__(256) reorder_w_f16(
    const float* __restrict__ src, __half* __restrict__ dst)
{
    int i = blockIdx.x * blockDim.x + threadIdx.x;
    if (i >= 512 * KCONV) return;
    int dout = i / KCONV;
    int k    = i - dout * KCONV;
    int tap  = k >> 9;
    int din  = k & 511;
    dst[i] = __float2half(src[dout * KCONV + din * 5 + tap]);
}

// concat(obj, motion) -> fp16 (2560, 1024); vector x8
__global__ void __launch_bounds__(256) concat_f16(
    const float* __restrict__ obj, const float* __restrict__ motion,
    __half* __restrict__ A)
{
    int i = blockIdx.x * blockDim.x + threadIdx.x;      // 2560*128
    if (i >= 2560 * 128) return;
    int row = i >> 7;
    int c8  = (i & 127) << 3;
    int b = row / 20, p = row - b * 20;
    const float* s = (p < P_) ? obj    + ((size_t)(b * P_ + p      )) * 1024 + c8
                              : motion + ((size_t)(b * P_ + p - P_ )) * 1024 + c8;
    const float4 v0 = *(const float4*)s;
    const float4 v1 = *(const float4*)(s + 4);
    __half h[8];
    h[0] = __float2half(v0.x); h[1] = __float2half(v0.y);
    h[2] = __float2half(v0.z); h[3] = __float2half(v0.w);
    h[4] = __float2half(v1.x); h[5] = __float2half(v1.y);
    h[6] = __float2half(v1.z); h[7] = __float2half(v1.w);
    *(uint4*)(A + (size_t)row * KPSL + c8) = *(const uint4*)h;
}

// ---------------- mma.sync GEMM (single pass fp16) -----------------------------
// C[M x 512] = A * B^T + bias
// CTA tile 128 x 128, BK=32, 256 threads (2x4 warps, warp tile 64x32),
// double-buffered cp.async. smem tile: 128 rows x pitch 40 half (80 B).
// AMODE 0: plain A rows (pitch K); AMODE 1: conv shifted view of (4096,512) fp16:
//          k = tap*512 + din, A row = grow + tap - 2 (zero if s+tap-2 out of [0,32))
// EPI 0: C = acc+bias
// EPI 1: C = acc+bias, H = fp16(relu(C))
// EPI 2: H = fp16(relu(acc+bias)) only
// EPI 3: C += 0.3*(acc+bias)
#define PITCH32 20          // u32 per row
#define MATB    10240u      // bytes per matrix tile
#define STAGEB  (2u * MATB) // A, B

template<int AMODE>
__device__ __forceinline__ void load_stage(
    uint32_t sb, int t,
    const __half* __restrict__ A, const __half* __restrict__ B,
    int row0, int col0, int K, int k0)
{
    // A tile
#pragma unroll
    for (int j = 0; j < 2; j++) {
        const int cid = j * 256 + t;           // 512 chunks: row = cid/4, ch = cid%4
        const int r  = cid >> 2, ch = cid & 3;
        const uint32_t sa = sb + (uint32_t)(r * 80 + ch * 16);
        if (AMODE == 0) {
            cp16(sa, A + (size_t)(row0 + r) * K + k0 + ch * 8);
        } else {
            const int grow = row0 + r;
            const int tap  = k0 >> 9;
            const int din0 = (k0 & 511) + ch * 8;
            const int s2   = (grow & 31) + tap - 2;
            const uint32_t ok = (s2 >= 0 && s2 < SEQ) ? 16u : 0u;
            const int srow = ok ? (grow + tap - 2) : grow;
            cp16z(sa, A + (size_t)srow * DIMN + din0, ok);
        }
    }
    // B tile
#pragma unroll
    for (int j = 0; j < 2; j++) {
        const int cid = j * 256 + t;
        const int r  = cid >> 2, ch = cid & 3;
        cp16(sb + MATB + (uint32_t)(r * 80 + ch * 16),
             B + (size_t)(col0 + r) * K + k0 + ch * 8);
    }
}

template<int AMODE, int EPI>
__global__ void __launch_bounds__(256) gemm_mma(
    const __half* __restrict__ A, const __half* __restrict__ B,
    const float* __restrict__ bias, float* __restrict__ C,
    __half* __restrict__ H, int K)
{
    extern __shared__ char smem[];
    const uint32_t sbase = smem_u32(smem);
    const int t = threadIdx.x;
    const int wid = t >> 5, lane = t & 31;
    const int warp_m = wid >> 2, warp_n = wid & 3;
    const int tr = lane >> 2, tc = lane & 3;
    const int row0 = blockIdx.y * 128;
    const int col0 = blockIdx.x * 128;

    float acc[4][4][4];
#pragma unroll
    for (int i = 0; i < 4; i++)
#pragma unroll
        for (int j = 0; j < 4; j++)
#pragma unroll
            for (int e = 0; e < 4; e++) acc[i][j][e] = 0.f;

    const int nch = K >> 5;

    load_stage<AMODE>(sbase, t, A, B, row0, col0, K, 0);
    cp_commit();

    for (int i = 0; i < nch; i++) {
        const int cur = i & 1;
        if (i + 1 < nch) {
            load_stage<AMODE>(sbase + (cur ^ 1) * STAGEB, t, A, B,
                              row0, col0, K, (i + 1) * 32);
            cp_commit();
            cp_wait<1>();
        } else {
            cp_wait<0>();
        }
        __syncthreads();

        const uint32_t* S  = (const uint32_t*)(smem + cur * STAGEB);
        const uint32_t* pA = S;
        const uint32_t* pB = S + MATB / 4;
#pragma unroll
        for (int k16 = 0; k16 < 2; k16++) {
            const int c = k16 * 8 + tc;
            uint32_t b0[4], b1[4];
#pragma unroll
            for (int nt = 0; nt < 4; nt++) {
                const int n = warp_n * 32 + nt * 8 + tr;
                b0[nt] = pB[n * PITCH32 + c];
                b1[nt] = pB[n * PITCH32 + c + 4];
            }
#pragma unroll
            for (int mt = 0; mt < 4; mt++) {
                const int r = warp_m * 64 + mt * 16 + tr;
                const uint32_t a0 = pA[r * PITCH32 + c];
                const uint32_t a1 = pA[(r + 8) * PITCH32 + c];
                const uint32_t a2 = pA[r * PITCH32 + c + 4];
                const uint32_t a3 = pA[(r + 8) * PITCH32 + c + 4];
#pragma unroll
                for (int nt = 0; nt < 4; nt++)
                    mma_f16(acc[mt][nt], a0, a1, a2, a3, b0[nt], b1[nt]);
            }
        }
        __syncthreads();
    }

    // epilogue
#pragma unroll
    for (int mt = 0; mt < 4; mt++) {
        const int r0 = row0 + warp_m * 64 + mt * 16 + tr;
#pragma unroll
        for (int nt = 0; nt < 4; nt++) {
            const int cc = col0 + warp_n * 32 + nt * 8 + tc * 2;
            const float bx = __ldg(bias + cc), by = __ldg(bias + cc + 1);
            float2 v0 = make_float2(acc[mt][nt][0] + bx, acc[mt][nt][1] + by);
            float2 v1 = make_float2(acc[mt][nt][2] + bx, acc[mt][nt][3] + by);
            float* p0 = C + (size_t)r0 * DIMN + cc;
            float* p1 = C + (size_t)(r0 + 8) * DIMN + cc;
            if (EPI == 3) {
                float2 o0 = *(const float2*)p0;
                float2 o1 = *(const float2*)p1;
                v0.x = o0.x + 0.3f * v0.x;  v0.y = o0.y + 0.3f * v0.y;
                v1.x = o1.x + 0.3f * v1.x;  v1.y = o1.y + 0.3f * v1.y;
            }
            if (EPI != 2) {
                *(float2*)p0 = v0;
                *(float2*)p1 = v1;
            }
            if (EPI == 1 || EPI == 2) {
                __half2 h0, h1;
                h0.x = __float2half(fmaxf(v0.x, 0.f));
                h0.y = __float2half(fmaxf(v0.y, 0.f));
                h1.x = __float2half(fmaxf(v1.x, 0.f));
                h1.y = __float2half(fmaxf(v1.y, 0.f));
                *(__half2*)(H + (size_t)r0 * DIMN + cc)       = h0;
                *(__half2*)(H + (size_t)(r0 + 8) * DIMN + cc) = h1;
            }
        }
    }
}

// ---------------- per-batch tail ------------------------------------------------
__global__ void __launch_bounds__(256) final_kernel(
    const float* __restrict__ alpha_all,  // (128, 32, 20)
    const float* __restrict__ att_mask,   // (128, 1, 32)
    const float* __restrict__ ln_g, const float* __restrict__ ln_b,
    const float* __restrict__ sv_w, const float* __restrict__ sv_b,
    const float* __restrict__ ss_w, const float* __restrict__ ss_b,
    const float* __restrict__ cl_w, const float* __restrict__ cl_b,
    float* __restrict__ out)              // (128, 6)
{
    const int b    = blockIdx.x;
    const int t    = threadIdx.x;
    const int warp = t >> 5;
    const int lane = t & 31;

    __shared__ float spt [NTOP][DIMN];
    __shared__ float sagg[NTOP][DIMN];
    __shared__ float sc  [NTOP][DIMN];
    __shared__ float adj [SEQ][NTOP];
    __shared__ float sums[20];
    __shared__ int   idxs[NTOP];
    __shared__ float smask[SEQ];

    if (t < SEQ) smask[t] = att_mask[b * SEQ + t];
    __syncthreads();

    if (t < 20) {
        float s = 0.f;
        for (int si = 0; si < SEQ; si++)
            s = fmaf(alpha_all[((size_t)b * SEQ + si) * 20 + t], smask[si], s);
        sums[t] = s;
    }
    __syncthreads();

    if (t == 0) {   // lax.top_k: descending, first index on ties
        unsigned used = 0;
        for (int k = 0; k < NTOP; k++) {
            int best = 0; float bv = -3.4e38f;
            for (int p = 0; p < 20; p++)
                if (!((used >> p) & 1u) && sums[p] > bv) { bv = sums[p]; best = p; }
            used |= (1u << best);
            idxs[k] = best;
        }
    }
    __syncthreads();

    for (int i = t; i < NTOP * DIMN; i += 256) {
        const int k = i >> 9, d = i & 511;
        spt[k][d] = g_psl[((size_t)b * 20 + idxs[k]) * DIMN + d];
    }
    __syncthreads();

    for (int pair = warp; pair < SEQ * NTOP; pair += 8) {
        const int s = pair / NTOP;
        const int k = pair - s * NTOP;
        const float* xr = g_X + ((size_t)b * SEQ + s) * DIMN;
        float acc = 0.f;
        for (int d = lane; d < DIMN; d += 32)
            acc = fmaf(xr[d], spt[k][d], acc);
#pragma unroll
        for (int o = 16; o > 0; o >>= 1)
            acc += __shfl_down_sync(0xffffffffu, acc, o);
        if (lane == 0) {
            const float v = acc * 0.04419417382415922f;
            adj[s][k] = (smask[s] > 0.f) ? v : -9.0e15f;
        }
    }
    __syncthreads();

    if (warp < NTOP) {
        const int k = warp;
        float v = adj[lane][k];
        float m = v;
#pragma unroll
        for (int o = 16; o > 0; o >>= 1)
            m = fmaxf(m, __shfl_xor_sync(0xffffffffu, m, o));
        const float e = expf(v - m);
        float ss = e;
#pragma unroll
        for (int o = 16; o > 0; o >>= 1)
            ss += __shfl_xor_sync(0xffffffffu, ss, o);
        adj[lane][k] = e / ss;
    }
    __syncthreads();

    for (int d = t; d < DIMN; d += 256) {
        float a[NTOP];
#pragma unroll
        for (int k = 0; k < NTOP; k++) a[k] = 0.f;
        for (int s = 0; s < SEQ; s++) {
            const float xv = g_X[((size_t)b * SEQ + s) * DIMN + d];
#pragma unroll
            for (int k = 0; k < NTOP; k++) a[k] = fmaf(xv, adj[s][k], a[k]);
        }
#pragma unroll
        for (int k = 0; k < NTOP; k++) sagg[k][d] = a[k];
    }
    __syncthreads();

    if (warp < NTOP) {
        const int k = warp;
        float sum = 0.f, sq = 0.f;
        for (int d = lane; d < DIMN; d += 32) {
            const float v = sagg[k][d];
            sum += v;
            sq = fmaf(v, v, sq);
        }
#pragma unroll
        for (int o = 16; o > 0; o >>= 1) {
            sum += __shfl_xor_sync(0xffffffffu, sum, o);
            sq  += __shfl_xor_sync(0xffffffffu, sq,  o);
        }
        const float mu  = sum * (1.f / DIMN);
        const float var = sq * (1.f / DIMN) - mu * mu;
        const float inv = rsqrtf(var + 1e-5f);
        for (int d = lane; d < DIMN; d += 32)
            sagg[k][d] = (sagg[k][d] - mu) * inv * ln_g[d] + ln_b[d];
    }
    __syncthreads();

    for (int idx = t; idx < NTOP * DIMN; idx += 256) {
        const int k = idx >> 9, d = idx & 511;
        float accv = sv_b[d], accs = ss_b[d];
        const float4* wv = (const float4*)(sv_w + (size_t)d * DIMN);
        const float4* ws = (const float4*)(ss_w + (size_t)d * DIMN);
        const float4* pv = (const float4*)(&spt[k][0]);
        const float4* pa = (const float4*)(&sagg[k][0]);
#pragma unroll 4
        for (int e = 0; e < DIMN / 4; e++) {
            const float4 a = pv[e], w = wv[e];
            accv = fmaf(a.x, w.x, fmaf(a.y, w.y, fmaf(a.z, w.z, fmaf(a.w, w.w, accv))));
            const float4 a2 = pa[e], w2 = ws[e];
            accs = fmaf(a2.x, w2.x, fmaf(a2.y, w2.y, fmaf(a2.z, w2.z, fmaf(a2.w, w2.w, accs))));
        }
        sc[k][d] = tanhf(accv) * tanhf(accs) * cl_w[d];
    }
    __syncthreads();

    if (warp < NTOP) {
        const int k = warp;
        float s = 0.f;
        for (int d = lane; d < DIMN; d += 32) s += sc[k][d];
#pragma unroll
        for (int o = 16; o > 0; o >>= 1)
            s += __shfl_xor_sync(0xffffffffu, s, o);
        if (lane == 0) {
            const float z = s + cl_b[0];
            out[b * NTOP + k] = 1.f / (1.f + expf(-z));
        }
    }
}

// ---------------- launch ----------------------------------------------------------
extern "C" void kernel_launch(void* const* d_in, const int* in_sizes, int n_in,
                              void* d_out, int out_size)
{
    const float* inputs   = (const float*)d_in[0];
    const float* obj      = (const float*)d_in[2];
    const float* motion   = (const float*)d_in[3];
    const float* att_mask = (const float*)d_in[4];
    const float* alpha    = (const float*)d_in[5];
    const float* conv_w   = (const float*)d_in[6];
    const float* conv_b   = (const float*)d_in[7];
    const float* res_w1   = (const float*)d_in[8];
    const float* res_b1   = (const float*)d_in[9];
    const float* res_w2   = (const float*)d_in[10];
    const float* res_b2   = (const float*)d_in[11];
    const float* psl_w    = (const float*)d_in[12];
    const float* psl_b    = (const float*)d_in[13];
    const float* ln_g     = (const float*)d_in[14];
    const float* ln_b     = (const float*)d_in[15];
    const float* sv_w     = (const float*)d_in[16];
    const float* sv_b     = (const float*)d_in[17];
    const float* ss_w     = (const float*)d_in[18];
    const float* ss_b     = (const float*)d_in[19];
    const float* cl_w     = (const float*)d_in[20];
    const float* cl_b     = (const float*)d_in[21];
    float* out = (float*)d_out;

    float *X, *PSL;
    __half *Xh, *Y1h, *A, *Wc, *W1, *W2, *Wp;
    cudaGetSymbolAddress((void**)&X,   g_X);
    cudaGetSymbolAddress((void**)&Xh,  g_Xh);
    cudaGetSymbolAddress((void**)&Y1h, g_Y1h);
    cudaGetSymbolAddress((void**)&PSL, g_psl);
    cudaGetSymbolAddress((void**)&A,   g_A);
    cudaGetSymbolAddress((void**)&Wc,  g_Wc);
    cudaGetSymbolAddress((void**)&W1,  g_W1);
    cudaGetSymbolAddress((void**)&W2,  g_W2);
    cudaGetSymbolAddress((void**)&Wp,  g_Wp);

    const int SMEM_BYTES = 2 * (int)STAGEB;   // 40960
    cudaFuncSetAttribute(gemm_mma<0,0>, cudaFuncAttributeMaxDynamicSharedMemorySize, SMEM_BYTES);
    cudaFuncSetAttribute(gemm_mma<0,1>, cudaFuncAttributeMaxDynamicSharedMemorySize, SMEM_BYTES);
    cudaFuncSetAttribute(gemm_mma<1,2>, cudaFuncAttributeMaxDynamicSharedMemorySize, SMEM_BYTES);
    cudaFuncSetAttribute(gemm_mma<1,3>, cudaFuncAttributeMaxDynamicSharedMemorySize, SMEM_BYTES);

    const dim3 blk(256);
    const dim3 gBig(4, 32);     // N=512/128, M=4096/128
    const dim3 gPsl(4, 20);     // M=2560/128

    // conversions
    f32_to_f16_pad<<<dim3((KBIGP / 8 + 255) / 256, 4096), 256>>>(inputs, A, KBIG, KBIGP);
    f32_to_f16_pad<<<dim3((KBIGP / 8 + 255) / 256, 512),  256>>>(conv_w, Wc, KBIG, KBIGP);
    reorder_w_f16<<<(512 * KCONV + 255) / 256, 256>>>(res_w1, W1);
    reorder_w_f16<<<(512 * KCONV + 255) / 256, 256>>>(res_w2, W2);
    f32_to_f16_pad<<<dim3((KPSL / 8 + 255) / 256, 512),   256>>>(psl_w, Wp, KPSL, KPSL);

    // GEMM1: x = inputs @ conv_w^T + conv_b ; also Xh = fp16(relu(x))
    gemm_mma<0, 1><<<gBig, blk, SMEM_BYTES>>>(A, Wc, conv_b, X, Xh, KBIGP);

    // GEMM2 (fused im2col): Y1h = fp16(relu(conv1(Xh) + b1))
    gemm_mma<1, 2><<<gBig, blk, SMEM_BYTES>>>(Xh, W1, res_b1, X /*unused*/, Y1h, KCONV);

    // GEMM3 (fused im2col): X += 0.3 * (conv2(Y1h) + b2)
    gemm_mma<1, 3><<<gBig, blk, SMEM_BYTES>>>(Y1h, W2, res_b2, X, Xh /*unused*/, KCONV);

    // concat proposals -> A ; GEMM4: psl_all
    concat_f16<<<(2560 * 128 + 255) / 256, 256>>>(obj, motion, A);
    gemm_mma<0, 0><<<gPsl, blk, SMEM_BYTES>>>(A, Wp, psl_b, PSL, Xh /*unused*/, KPSL);

    // tail
    final_kernel<<<BS_, 256>>>(alpha, att_mask, ln_g, ln_b,
                               sv_w, sv_b, ss_w, ss_b, cl_w, cl_b, out);
}

// round 6
// speedup vs baseline: 4.0100x; 1.0519x over previous
#include <cuda_runtime.h>
#include <cuda_fp16.h>
#include <math.h>
#include <stdint.h>

#define BS_    128
#define SEQ    32
#define DIMN   512
#define P_     10
#define NTOP   6

#define KBIG   10000
#define KBIGP  10016            // padded to multiple of 32
#define KCONV  2560             // 512*5 (tap-major: k = tap*512 + din)
#define KPSL   1024

// ---------------- device scratch (no allocations allowed) -------------------
__device__ float  g_X  [BS_ * SEQ * DIMN];          // x fp32 (residual + tail)
__device__ __half g_Xh [BS_ * SEQ * DIMN];          // fp16(relu(x))
__device__ __half g_Y1h[BS_ * SEQ * DIMN];          // fp16(relu(y1))
__device__ float  g_psl[BS_ * 2 * P_ * DIMN];

__device__ __half g_A  [(size_t)4096 * KBIGP];      // big activation buffer
__device__ __half g_Wc [(size_t)512 * KBIGP];
__device__ __half g_W1 [512 * KCONV];
__device__ __half g_W2 [512 * KCONV];
__device__ __half g_Wp [512 * KPSL];

// ---------------- ptx helpers -------------------------------------------------
__device__ __forceinline__ void cp16(uint32_t sa, const void* g) {
    asm volatile("cp.async.cg.shared.global [%0], [%1], 16;\n" :: "r"(sa), "l"(g) : "memory");
}
__device__ __forceinline__ void cp16z(uint32_t sa, const void* g, uint32_t srcsize) {
    asm volatile("cp.async.cg.shared.global [%0], [%1], 16, %2;\n"
                 :: "r"(sa), "l"(g), "r"(srcsize) : "memory");
}
__device__ __forceinline__ void cp_commit() {
    asm volatile("cp.async.commit_group;\n" ::: "memory");
}
template<int N> __device__ __forceinline__ void cp_wait() {
    asm volatile("cp.async.wait_group %0;\n" :: "n"(N) : "memory");
}
__device__ __forceinline__ uint32_t smem_u32(const void* p) {
    uint32_t a;
    asm("{ .reg .u64 t; cvta.to.shared.u64 t, %1; cvt.u32.u64 %0, t; }" : "=r"(a) : "l"(p));
    return a;
}
__device__ __forceinline__ void ldmx4(uint32_t* r, uint32_t addr) {
    asm volatile("ldmatrix.sync.aligned.m8n8.x4.shared.b16 {%0,%1,%2,%3}, [%4];"
                 : "=r"(r[0]), "=r"(r[1]), "=r"(r[2]), "=r"(r[3]) : "r"(addr));
}
__device__ __forceinline__ void mma_f16(float* d,
    uint32_t a0, uint32_t a1, uint32_t a2, uint32_t a3,
    uint32_t b0, uint32_t b1)
{
    asm volatile(
        "mma.sync.aligned.m16n8k16.row.col.f32.f16.f16.f32 "
        "{%0,%1,%2,%3}, {%4,%5,%6,%7}, {%8,%9}, {%0,%1,%2,%3};"
        : "+f"(d[0]), "+f"(d[1]), "+f"(d[2]), "+f"(d[3])
        : "r"(a0), "r"(a1), "r"(a2), "r"(a3), "r"(b0), "r"(b1));
}

// ---------------- conversion kernels -------------------------------------------
__global__ void __launch_bounds__(256) f32_to_f16_pad(
    const float* __restrict__ src, __half* __restrict__ dst, int K, int Kpad)
{
    const int row = blockIdx.y;
    const int c8  = (blockIdx.x * blockDim.x + threadIdx.x) << 3;
    if (c8 >= Kpad) return;
    const float* s = src + (size_t)row * K + c8;
    __half h[8];
    if (c8 + 8 <= K) {
        const float4 v0 = *(const float4*)s;
        const float4 v1 = *(const float4*)(s + 4);
        h[0] = __float2half(v0.x); h[1] = __float2half(v0.y);
        h[2] = __float2half(v0.z); h[3] = __float2half(v0.w);
        h[4] = __float2half(v1.x); h[5] = __float2half(v1.y);
        h[6] = __float2half(v1.z); h[7] = __float2half(v1.w);
    } else {
#pragma unroll
        for (int j = 0; j < 8; j++)
            h[j] = (c8 + j < K) ? __float2half(s[j]) : __float2half(0.f);
    }
    *(uint4*)(dst + (size_t)row * Kpad + c8) = *(const uint4*)h;
}

// both res weights (512, 512, 5) -> fp16 (512, 2560), k = tap*512 + din
__global__ void __launch_bounds__(256) reorder_w2_f16(
    const float* __restrict__ src1, __half* __restrict__ dst1,
    const float* __restrict__ src2, __half* __restrict__ dst2)
{
    int i = blockIdx.x * blockDim.x + threadIdx.x;
    const int n1 = 512 * KCONV;
    const float* src = (i < n1) ? src1 : src2;
    __half* dst = (i < n1) ? dst1 : dst2;
    int ii = (i < n1) ? i : i - n1;
    if (ii >= n1) return;
    int dout = ii / KCONV;
    int k    = ii - dout * KCONV;
    int tap  = k >> 9;
    int din  = k & 511;
    dst[ii] = __float2half(src[dout * KCONV + din * 5 + tap]);
}

// concat(obj, motion) -> fp16 (2560, 1024)
__global__ void __launch_bounds__(256) concat_f16(
    const float* __restrict__ obj, const float* __restrict__ motion,
    __half* __restrict__ A)
{
    int i = blockIdx.x * blockDim.x + threadIdx.x;      // 2560*128
    if (i >= 2560 * 128) return;
    int row = i >> 7;
    int c8  = (i & 127) << 3;
    int b = row / 20, p = row - b * 20;
    const float* s = (p < P_) ? obj    + ((size_t)(b * P_ + p      )) * 1024 + c8
                              : motion + ((size_t)(b * P_ + p - P_ )) * 1024 + c8;
    const float4 v0 = *(const float4*)s;
    const float4 v1 = *(const float4*)(s + 4);
    __half h[8];
    h[0] = __float2half(v0.x); h[1] = __float2half(v0.y);
    h[2] = __float2half(v0.z); h[3] = __float2half(v0.w);
    h[4] = __float2half(v1.x); h[5] = __float2half(v1.y);
    h[6] = __float2half(v1.z); h[7] = __float2half(v1.w);
    *(uint4*)(A + (size_t)row * KPSL + c8) = *(const uint4*)h;
}

// ---------------- mma.sync GEMM, 4-stage cp.async + ldmatrix -------------------
// C[M x 512] = A * B^T + bias. CTA tile 128x128, BK=32, 256 thr (2x4 warps).
// smem tile: 128 rows x 80 B; stage = A+B = 20480 B; 4 stages = 81920 B.
// AMODE 0: plain rows (pitch K); AMODE 1: conv shifted rows of (4096,512) fp16.
// EPI 0: C=acc+b | 1: C=acc+b, H=h(relu) | 2: H only | 3: C += 0.3*(acc+b)
#define MATB    10240u
#define STAGEB  (2u * MATB)
#define NSTAGE  4

template<int AMODE>
__device__ __forceinline__ void load_stage(
    uint32_t sb, int t,
    const __half* __restrict__ A, const __half* __restrict__ B,
    int row0, int col0, int K, int k0)
{
#pragma unroll
    for (int j = 0; j < 2; j++) {
        const int cid = j * 256 + t;           // 512 chunks: row = cid/4, ch = cid%4
        const int r  = cid >> 2, ch = cid & 3;
        const uint32_t sa = sb + (uint32_t)(r * 80 + ch * 16);
        if (AMODE == 0) {
            cp16(sa, A + (size_t)(row0 + r) * K + k0 + ch * 8);
        } else {
            const int grow = row0 + r;
            const int tap  = k0 >> 9;
            const int din0 = (k0 & 511) + ch * 8;
            const int s2   = (grow & 31) + tap - 2;
            const uint32_t ok = (s2 >= 0 && s2 < SEQ) ? 16u : 0u;
            const int srow = ok ? (grow + tap - 2) : grow;
            cp16z(sa, A + (size_t)srow * DIMN + din0, ok);
        }
    }
#pragma unroll
    for (int j = 0; j < 2; j++) {
        const int cid = j * 256 + t;
        const int r  = cid >> 2, ch = cid & 3;
        cp16(sb + MATB + (uint32_t)(r * 80 + ch * 16),
             B + (size_t)(col0 + r) * K + k0 + ch * 8);
    }
}

template<int AMODE, int EPI>
__global__ void __launch_bounds__(256) gemm_mma(
    const __half* __restrict__ A, const __half* __restrict__ B,
    const float* __restrict__ bias, float* __restrict__ C,
    __half* __restrict__ H, int K)
{
    extern __shared__ char smem[];
    const uint32_t sbase = smem_u32(smem);
    const int t = threadIdx.x;
    const int wid = t >> 5, lane = t & 31;
    const int warp_m = wid >> 2, warp_n = wid & 3;
    const int tr = lane >> 2, tc = lane & 3;
    const int row0 = blockIdx.y * 128;
    const int col0 = blockIdx.x * 128;

    // ldmatrix lane offsets (within a stage)
    const uint32_t a_off = (uint32_t)((warp_m * 64 + (lane & 15)) * 80 + (lane >> 4) * 16);
    const uint32_t b_off = MATB +
        (uint32_t)((warp_n * 32 + (lane & 7) + ((lane >> 4) << 3)) * 80 + ((lane >> 3) & 1) * 16);

    float acc[4][4][4];
#pragma unroll
    for (int i = 0; i < 4; i++)
#pragma unroll
        for (int j = 0; j < 4; j++)
#pragma unroll
            for (int e = 0; e < 4; e++) acc[i][j][e] = 0.f;

    const int nch = K >> 5;

    // prologue: stages 0..2
#pragma unroll
    for (int s = 0; s < NSTAGE - 1; s++) {
        if (s < nch)
            load_stage<AMODE>(sbase + s * STAGEB, t, A, B, row0, col0, K, s * 32);
        cp_commit();
    }

    for (int i = 0; i < nch; i++) {
        cp_wait<NSTAGE - 2>();
        __syncthreads();

        if (i + NSTAGE - 1 < nch)
            load_stage<AMODE>(sbase + ((i + NSTAGE - 1) & (NSTAGE - 1)) * STAGEB,
                              t, A, B, row0, col0, K, (i + NSTAGE - 1) * 32);
        cp_commit();

        const uint32_t sb = sbase + (uint32_t)(i & (NSTAGE - 1)) * STAGEB;
#pragma unroll
        for (int k16 = 0; k16 < 2; k16++) {
            uint32_t a[4][4], b[4][2];
#pragma unroll
            for (int mt = 0; mt < 4; mt++)
                ldmx4(a[mt], sb + a_off + (uint32_t)(mt * 1280 + k16 * 32));
#pragma unroll
            for (int j = 0; j < 2; j++) {
                uint32_t r[4];
                ldmx4(r, sb + b_off + (uint32_t)(j * 1280 + k16 * 32));
                b[2 * j][0] = r[0]; b[2 * j][1] = r[1];
                b[2 * j + 1][0] = r[2]; b[2 * j + 1][1] = r[3];
            }
#pragma unroll
            for (int mt = 0; mt < 4; mt++)
#pragma unroll
                for (int nt = 0; nt < 4; nt++)
                    mma_f16(acc[mt][nt], a[mt][0], a[mt][1], a[mt][2], a[mt][3],
                            b[nt][0], b[nt][1]);
        }
    }

    // epilogue
#pragma unroll
    for (int mt = 0; mt < 4; mt++) {
        const int r0 = row0 + warp_m * 64 + mt * 16 + tr;
#pragma unroll
        for (int nt = 0; nt < 4; nt++) {
            const int cc = col0 + warp_n * 32 + nt * 8 + tc * 2;
            const float bx = __ldg(bias + cc), by = __ldg(bias + cc + 1);
            float2 v0 = make_float2(acc[mt][nt][0] + bx, acc[mt][nt][1] + by);
            float2 v1 = make_float2(acc[mt][nt][2] + bx, acc[mt][nt][3] + by);
            float* p0 = C + (size_t)r0 * DIMN + cc;
            float* p1 = C + (size_t)(r0 + 8) * DIMN + cc;
            if (EPI == 3) {
                float2 o0 = *(const float2*)p0;
                float2 o1 = *(const float2*)p1;
                v0.x = o0.x + 0.3f * v0.x;  v0.y = o0.y + 0.3f * v0.y;
                v1.x = o1.x + 0.3f * v1.x;  v1.y = o1.y + 0.3f * v1.y;
            }
            if (EPI != 2) {
                *(float2*)p0 = v0;
                *(float2*)p1 = v1;
            }
            if (EPI == 1 || EPI == 2) {
                __half2 h0, h1;
                h0.x = __float2half(fmaxf(v0.x, 0.f));
                h0.y = __float2half(fmaxf(v0.y, 0.f));
                h1.x = __float2half(fmaxf(v1.x, 0.f));
                h1.y = __float2half(fmaxf(v1.y, 0.f));
                *(__half2*)(H + (size_t)r0 * DIMN + cc)       = h0;
                *(__half2*)(H + (size_t)(r0 + 8) * DIMN + cc) = h1;
            }
        }
    }
}

// ---------------- per-batch tail ------------------------------------------------
__global__ void __launch_bounds__(256) final_kernel(
    const float* __restrict__ alpha_all,  // (128, 32, 20)
    const float* __restrict__ att_mask,   // (128, 1, 32)
    const float* __restrict__ ln_g, const float* __restrict__ ln_b,
    const float* __restrict__ sv_w, const float* __restrict__ sv_b,
    const float* __restrict__ ss_w, const float* __restrict__ ss_b,
    const float* __restrict__ cl_w, const float* __restrict__ cl_b,
    float* __restrict__ out)              // (128, 6)
{
    const int b    = blockIdx.x;
    const int t    = threadIdx.x;
    const int warp = t >> 5;
    const int lane = t & 31;

    __shared__ float spt [NTOP][DIMN];
    __shared__ float sagg[NTOP][DIMN];
    __shared__ float sc  [NTOP][DIMN];
    __shared__ float adj [SEQ][NTOP];
    __shared__ float sums[20];
    __shared__ int   idxs[NTOP];
    __shared__ float smask[SEQ];

    if (t < SEQ) smask[t] = att_mask[b * SEQ + t];
    __syncthreads();

    if (t < 20) {
        float s = 0.f;
        for (int si = 0; si < SEQ; si++)
            s = fmaf(alpha_all[((size_t)b * SEQ + si) * 20 + t], smask[si], s);
        sums[t] = s;
    }
    __syncthreads();

    if (t == 0) {   // lax.top_k: descending, first index on ties
        unsigned used = 0;
        for (int k = 0; k < NTOP; k++) {
            int best = 0; float bv = -3.4e38f;
            for (int p = 0; p < 20; p++)
                if (!((used >> p) & 1u) && sums[p] > bv) { bv = sums[p]; best = p; }
            used |= (1u << best);
            idxs[k] = best;
        }
    }
    __syncthreads();

    for (int i = t; i < NTOP * DIMN; i += 256) {
        const int k = i >> 9, d = i & 511;
        spt[k][d] = g_psl[((size_t)b * 20 + idxs[k]) * DIMN + d];
    }
    __syncthreads();

    for (int pair = warp; pair < SEQ * NTOP; pair += 8) {
        const int s = pair / NTOP;
        const int k = pair - s * NTOP;
        const float* xr = g_X + ((size_t)b * SEQ + s) * DIMN;
        float acc = 0.f;
        for (int d = lane; d < DIMN; d += 32)
            acc = fmaf(xr[d], spt[k][d], acc);
#pragma unroll
        for (int o = 16; o > 0; o >>= 1)
            acc += __shfl_down_sync(0xffffffffu, acc, o);
        if (lane == 0) {
            const float v = acc * 0.04419417382415922f;
            adj[s][k] = (smask[s] > 0.f) ? v : -9.0e15f;
        }
    }
    __syncthreads();

    if (warp < NTOP) {
        const int k = warp;
        float v = adj[lane][k];
        float m = v;
#pragma unroll
        for (int o = 16; o > 0; o >>= 1)
            m = fmaxf(m, __shfl_xor_sync(0xffffffffu, m, o));
        const float e = expf(v - m);
        float ss = e;
#pragma unroll
        for (int o = 16; o > 0; o >>= 1)
            ss += __shfl_xor_sync(0xffffffffu, ss, o);
        adj[lane][k] = e / ss;
    }
    __syncthreads();

    for (int d = t; d < DIMN; d += 256) {
        float a[NTOP];
#pragma unroll
        for (int k = 0; k < NTOP; k++) a[k] = 0.f;
        for (int s = 0; s < SEQ; s++) {
            const float xv = g_X[((size_t)b * SEQ + s) * DIMN + d];
#pragma unroll
            for (int k = 0; k < NTOP; k++) a[k] = fmaf(xv, adj[s][k], a[k]);
        }
#pragma unroll
        for (int k = 0; k < NTOP; k++) sagg[k][d] = a[k];
    }
    __syncthreads();

    if (warp < NTOP) {
        const int k = warp;
        float sum = 0.f, sq = 0.f;
        for (int d = lane; d < DIMN; d += 32) {
            const float v = sagg[k][d];
            sum += v;
            sq = fmaf(v, v, sq);
        }
#pragma unroll
        for (int o = 16; o > 0; o >>= 1) {
            sum += __shfl_xor_sync(0xffffffffu, sum, o);
            sq  += __shfl_xor_sync(0xffffffffu, sq,  o);
        }
        const float mu  = sum * (1.f / DIMN);
        const float var = sq * (1.f / DIMN) - mu * mu;
        const float inv = rsqrtf(var + 1e-5f);
        for (int d = lane; d < DIMN; d += 32)
            sagg[k][d] = (sagg[k][d] - mu) * inv * ln_g[d] + ln_b[d];
    }
    __syncthreads();

    for (int idx = t; idx < NTOP * DIMN; idx += 256) {
        const int k = idx >> 9, d = idx & 511;
        float accv = sv_b[d], accs = ss_b[d];
        const float4* wv = (const float4*)(sv_w + (size_t)d * DIMN);
        const float4* ws = (const float4*)(ss_w + (size_t)d * DIMN);
        const float4* pv = (const float4*)(&spt[k][0]);
        const float4* pa = (const float4*)(&sagg[k][0]);
#pragma unroll 4
        for (int e = 0; e < DIMN / 4; e++) {
            const float4 a = pv[e], w = wv[e];
            accv = fmaf(a.x, w.x, fmaf(a.y, w.y, fmaf(a.z, w.z, fmaf(a.w, w.w, accv))));
            const float4 a2 = pa[e], w2 = ws[e];
            accs = fmaf(a2.x, w2.x, fmaf(a2.y, w2.y, fmaf(a2.z, w2.z, fmaf(a2.w, w2.w, accs))));
        }
        sc[k][d] = tanhf(accv) * tanhf(accs) * cl_w[d];
    }
    __syncthreads();

    if (warp < NTOP) {
        const int k = warp;
        float s = 0.f;
        for (int d = lane; d < DIMN; d += 32) s += sc[k][d];
#pragma unroll
        for (int o = 16; o > 0; o >>= 1)
            s += __shfl_xor_sync(0xffffffffu, s, o);
        if (lane == 0) {
            const float z = s + cl_b[0];
            out[b * NTOP + k] = 1.f / (1.f + expf(-z));
        }
    }
}

// ---------------- launch ----------------------------------------------------------
extern "C" void kernel_launch(void* const* d_in, const int* in_sizes, int n_in,
                              void* d_out, int out_size)
{
    const float* inputs   = (const float*)d_in[0];
    const float* obj      = (const float*)d_in[2];
    const float* motion   = (const float*)d_in[3];
    const float* att_mask = (const float*)d_in[4];
    const float* alpha    = (const float*)d_in[5];
    const float* conv_w   = (const float*)d_in[6];
    const float* conv_b   = (const float*)d_in[7];
    const float* res_w1   = (const float*)d_in[8];
    const float* res_b1   = (const float*)d_in[9];
    const float* res_w2   = (const float*)d_in[10];
    const float* res_b2   = (const float*)d_in[11];
    const float* psl_w    = (const float*)d_in[12];
    const float* psl_b    = (const float*)d_in[13];
    const float* ln_g     = (const float*)d_in[14];
    const float* ln_b     = (const float*)d_in[15];
    const float* sv_w     = (const float*)d_in[16];
    const float* sv_b     = (const float*)d_in[17];
    const float* ss_w     = (const float*)d_in[18];
    const float* ss_b     = (const float*)d_in[19];
    const float* cl_w     = (const float*)d_in[20];
    const float* cl_b     = (const float*)d_in[21];
    float* out = (float*)d_out;

    float *X, *PSL;
    __half *Xh, *Y1h, *A, *Wc, *W1, *W2, *Wp;
    cudaGetSymbolAddress((void**)&X,   g_X);
    cudaGetSymbolAddress((void**)&Xh,  g_Xh);
    cudaGetSymbolAddress((void**)&Y1h, g_Y1h);
    cudaGetSymbolAddress((void**)&PSL, g_psl);
    cudaGetSymbolAddress((void**)&A,   g_A);
    cudaGetSymbolAddress((void**)&Wc,  g_Wc);
    cudaGetSymbolAddress((void**)&W1,  g_W1);
    cudaGetSymbolAddress((void**)&W2,  g_W2);
    cudaGetSymbolAddress((void**)&Wp,  g_Wp);

    const int SMEM_BYTES = NSTAGE * (int)STAGEB;   // 81920
    cudaFuncSetAttribute(gemm_mma<0,0>, cudaFuncAttributeMaxDynamicSharedMemorySize, SMEM_BYTES);
    cudaFuncSetAttribute(gemm_mma<0,1>, cudaFuncAttributeMaxDynamicSharedMemorySize, SMEM_BYTES);
    cudaFuncSetAttribute(gemm_mma<1,2>, cudaFuncAttributeMaxDynamicSharedMemorySize, SMEM_BYTES);
    cudaFuncSetAttribute(gemm_mma<1,3>, cudaFuncAttributeMaxDynamicSharedMemorySize, SMEM_BYTES);

    const dim3 blk(256);
    const dim3 gBig(4, 32);     // N=512/128, M=4096/128
    const dim3 gPsl(4, 20);     // M=2560/128

    // conversions
    f32_to_f16_pad<<<dim3((KBIGP / 8 + 255) / 256, 4096), 256>>>(inputs, A, KBIG, KBIGP);
    f32_to_f16_pad<<<dim3((KBIGP / 8 + 255) / 256, 512),  256>>>(conv_w, Wc, KBIG, KBIGP);
    reorder_w2_f16<<<(2 * 512 * KCONV + 255) / 256, 256>>>(res_w1, W1, res_w2, W2);
    f32_to_f16_pad<<<dim3((KPSL / 8 + 255) / 256, 512),   256>>>(psl_w, Wp, KPSL, KPSL);

    // GEMM1: x = inputs @ conv_w^T + conv_b ; also Xh = fp16(relu(x))
    gemm_mma<0, 1><<<gBig, blk, SMEM_BYTES>>>(A, Wc, conv_b, X, Xh, KBIGP);

    // GEMM2 (fused im2col): Y1h = fp16(relu(conv1(Xh) + b1))
    gemm_mma<1, 2><<<gBig, blk, SMEM_BYTES>>>(Xh, W1, res_b1, X /*unused*/, Y1h, KCONV);

    // GEMM3 (fused im2col): X += 0.3 * (conv2(Y1h) + b2)
    gemm_mma<1, 3><<<gBig, blk, SMEM_BYTES>>>(Y1h, W2, res_b2, X, Xh /*unused*/, KCONV);

    // concat proposals -> A ; GEMM4: psl_all
    concat_f16<<<(2560 * 128 + 255) / 256, 256>>>(obj, motion, A);
    gemm_mma<0, 0><<<gPsl, blk, SMEM_BYTES>>>(A, Wp, psl_b, PSL, Xh /*unused*/, KPSL);

    // tail
    final_kernel<<<BS_, 256>>>(alpha, att_mask, ln_g, ln_b,
                               sv_w, sv_b, ss_w, ss_b, cl_w, cl_b, out);
}

// round 7
// speedup vs baseline: 4.2380x; 1.0569x over previous
#include <cuda_runtime.h>
#include <cuda_fp16.h>
#include <math.h>
#include <stdint.h>

#define BS_    128
#define SEQ    32
#define DIMN   512
#define P_     10
#define NTOP   6

#define KBIG   10000
#define KBIGP  10016            // padded to multiple of 32
#define KCONV  2560             // 512*5 (tap-major: k = tap*512 + din)
#define KPSL   1024

// ---------------- device scratch (no allocations allowed) -------------------
__device__ float  g_X  [BS_ * SEQ * DIMN];          // x fp32 (residual + tail)
__device__ __half g_Xh [BS_ * SEQ * DIMN];          // fp16(relu(x))
__device__ __half g_Y1h[BS_ * SEQ * DIMN];          // fp16(relu(y1))
__device__ float  g_psl[BS_ * 2 * P_ * DIMN];

__device__ __half g_A  [(size_t)4096 * KBIGP];      // big activation buffer
__device__ __half g_Wc [(size_t)512 * KBIGP];
__device__ __half g_W1 [512 * KCONV];
__device__ __half g_W2 [512 * KCONV];
__device__ __half g_Wp [512 * KPSL];

// ---------------- ptx helpers -------------------------------------------------
__device__ __forceinline__ void cp16(uint32_t sa, const void* g) {
    asm volatile("cp.async.cg.shared.global [%0], [%1], 16;\n" :: "r"(sa), "l"(g) : "memory");
}
__device__ __forceinline__ void cp16z(uint32_t sa, const void* g, uint32_t srcsize) {
    asm volatile("cp.async.cg.shared.global [%0], [%1], 16, %2;\n"
                 :: "r"(sa), "l"(g), "r"(srcsize) : "memory");
}
__device__ __forceinline__ void cp_commit() {
    asm volatile("cp.async.commit_group;\n" ::: "memory");
}
template<int N> __device__ __forceinline__ void cp_wait() {
    asm volatile("cp.async.wait_group %0;\n" :: "n"(N) : "memory");
}
__device__ __forceinline__ uint32_t smem_u32(const void* p) {
    uint32_t a;
    asm("{ .reg .u64 t; cvta.to.shared.u64 t, %1; cvt.u32.u64 %0, t; }" : "=r"(a) : "l"(p));
    return a;
}
__device__ __forceinline__ void ldmx4(uint32_t* r, uint32_t addr) {
    asm volatile("ldmatrix.sync.aligned.m8n8.x4.shared.b16 {%0,%1,%2,%3}, [%4];"
                 : "=r"(r[0]), "=r"(r[1]), "=r"(r[2]), "=r"(r[3]) : "r"(addr));
}
__device__ __forceinline__ void mma_f16(float* d,
    uint32_t a0, uint32_t a1, uint32_t a2, uint32_t a3,
    uint32_t b0, uint32_t b1)
{
    asm volatile(
        "mma.sync.aligned.m16n8k16.row.col.f32.f16.f16.f32 "
        "{%0,%1,%2,%3}, {%4,%5,%6,%7}, {%8,%9}, {%0,%1,%2,%3};"
        : "+f"(d[0]), "+f"(d[1]), "+f"(d[2]), "+f"(d[3])
        : "r"(a0), "r"(a1), "r"(a2), "r"(a3), "r"(b0), "r"(b1));
}

// ---------------- conversion kernels -------------------------------------------
__global__ void __launch_bounds__(256) f32_to_f16_pad(
    const float* __restrict__ src, __half* __restrict__ dst, int K, int Kpad)
{
    const int row = blockIdx.y;
    const int c8  = (blockIdx.x * blockDim.x + threadIdx.x) << 3;
    if (c8 >= Kpad) return;
    const float* s = src + (size_t)row * K + c8;
    __half h[8];
    if (c8 + 8 <= K) {
        const float4 v0 = *(const float4*)s;
        const float4 v1 = *(const float4*)(s + 4);
        h[0] = __float2half(v0.x); h[1] = __float2half(v0.y);
        h[2] = __float2half(v0.z); h[3] = __float2half(v0.w);
        h[4] = __float2half(v1.x); h[5] = __float2half(v1.y);
        h[6] = __float2half(v1.z); h[7] = __float2half(v1.w);
    } else {
#pragma unroll
        for (int j = 0; j < 8; j++)
            h[j] = (c8 + j < K) ? __float2half(s[j]) : __float2half(0.f);
    }
    *(uint4*)(dst + (size_t)row * Kpad + c8) = *(const uint4*)h;
}

// both res weights (512, 512, 5) -> fp16 (512, 2560), k = tap*512 + din
__global__ void __launch_bounds__(256) reorder_w2_f16(
    const float* __restrict__ src1, __half* __restrict__ dst1,
    const float* __restrict__ src2, __half* __restrict__ dst2)
{
    int i = blockIdx.x * blockDim.x + threadIdx.x;
    const int n1 = 512 * KCONV;
    const float* src = (i < n1) ? src1 : src2;
    __half* dst = (i < n1) ? dst1 : dst2;
    int ii = (i < n1) ? i : i - n1;
    if (ii >= n1) return;
    int dout = ii / KCONV;
    int k    = ii - dout * KCONV;
    int tap  = k >> 9;
    int din  = k & 511;
    dst[ii] = __float2half(src[dout * KCONV + din * 5 + tap]);
}

// concat(obj, motion) -> fp16 (2560, 1024)
__global__ void __launch_bounds__(256) concat_f16(
    const float* __restrict__ obj, const float* __restrict__ motion,
    __half* __restrict__ A)
{
    int i = blockIdx.x * blockDim.x + threadIdx.x;      // 2560*128
    if (i >= 2560 * 128) return;
    int row = i >> 7;
    int c8  = (i & 127) << 3;
    int b = row / 20, p = row - b * 20;
    const float* s = (p < P_) ? obj    + ((size_t)(b * P_ + p      )) * 1024 + c8
                              : motion + ((size_t)(b * P_ + p - P_ )) * 1024 + c8;
    const float4 v0 = *(const float4*)s;
    const float4 v1 = *(const float4*)(s + 4);
    __half h[8];
    h[0] = __float2half(v0.x); h[1] = __float2half(v0.y);
    h[2] = __float2half(v0.z); h[3] = __float2half(v0.w);
    h[4] = __float2half(v1.x); h[5] = __float2half(v1.y);
    h[6] = __float2half(v1.z); h[7] = __float2half(v1.w);
    *(uint4*)(A + (size_t)row * KPSL + c8) = *(const uint4*)h;
}

// ---------------- mma.sync GEMM, 4-stage cp.async + ldmatrix -------------------
// C[M x 512] = A * B^T + bias. CTA tile 128(M) x 64(N), BK=32, 128 thr
// (4 warps as 2x2, warp tile 64x32). smem stage = 128*80 + 64*80 = 15360 B;
// 4 stages = 61440 B -> 3 CTAs/SM.
// AMODE 0: plain rows (pitch K); AMODE 1: conv shifted rows of (4096,512) fp16.
// EPI 0: C=acc+b | 1: C=acc+b, H=h(relu) | 2: H only | 3: C += 0.3*(acc+b)
#define TILEN   64
#define MATA    10240u                 // 128 rows x 80 B
#define MATBB   5120u                  // 64 rows x 80 B
#define STAGEB  (MATA + MATBB)         // 15360
#define NSTAGE  4

template<int AMODE>
__device__ __forceinline__ void load_stage(
    uint32_t sb, int t,
    const __half* __restrict__ A, const __half* __restrict__ B,
    int row0, int col0, int K, int k0)
{
    // A tile: 512 chunks of 16B
#pragma unroll
    for (int j = 0; j < 4; j++) {
        const int cid = j * 128 + t;
        const int r  = cid >> 2, ch = cid & 3;
        const uint32_t sa = sb + (uint32_t)(r * 80 + ch * 16);
        if (AMODE == 0) {
            cp16(sa, A + (size_t)(row0 + r) * K + k0 + ch * 8);
        } else {
            const int grow = row0 + r;
            const int tap  = k0 >> 9;
            const int din0 = (k0 & 511) + ch * 8;
            const int s2   = (grow & 31) + tap - 2;
            const uint32_t ok = (s2 >= 0 && s2 < SEQ) ? 16u : 0u;
            const int srow = ok ? (grow + tap - 2) : grow;
            cp16z(sa, A + (size_t)srow * DIMN + din0, ok);
        }
    }
    // B tile: 256 chunks
#pragma unroll
    for (int j = 0; j < 2; j++) {
        const int cid = j * 128 + t;
        const int r  = cid >> 2, ch = cid & 3;
        cp16(sb + MATA + (uint32_t)(r * 80 + ch * 16),
             B + (size_t)(col0 + r) * K + k0 + ch * 8);
    }
}

template<int AMODE, int EPI>
__global__ void __launch_bounds__(128, 3) gemm_mma(
    const __half* __restrict__ A, const __half* __restrict__ B,
    const float* __restrict__ bias, float* __restrict__ C,
    __half* __restrict__ H, int K)
{
    extern __shared__ char smem[];
    const uint32_t sbase = smem_u32(smem);
    const int t = threadIdx.x;
    const int wid = t >> 5, lane = t & 31;
    const int warp_m = wid >> 1, warp_n = wid & 1;
    const int tr = lane >> 2, tc = lane & 3;
    const int row0 = blockIdx.y * 128;
    const int col0 = blockIdx.x * TILEN;

    const uint32_t a_off = (uint32_t)((warp_m * 64 + (lane & 15)) * 80 + (lane >> 4) * 16);
    const uint32_t b_off = MATA +
        (uint32_t)((warp_n * 32 + (lane & 7) + ((lane >> 4) << 3)) * 80 + ((lane >> 3) & 1) * 16);

    float acc[4][4][4];
#pragma unroll
    for (int i = 0; i < 4; i++)
#pragma unroll
        for (int j = 0; j < 4; j++)
#pragma unroll
            for (int e = 0; e < 4; e++) acc[i][j][e] = 0.f;

    const int nch = K >> 5;

#pragma unroll
    for (int s = 0; s < NSTAGE - 1; s++) {
        if (s < nch)
            load_stage<AMODE>(sbase + s * STAGEB, t, A, B, row0, col0, K, s * 32);
        cp_commit();
    }

    for (int i = 0; i < nch; i++) {
        cp_wait<NSTAGE - 2>();
        __syncthreads();

        if (i + NSTAGE - 1 < nch)
            load_stage<AMODE>(sbase + ((i + NSTAGE - 1) & (NSTAGE - 1)) * STAGEB,
                              t, A, B, row0, col0, K, (i + NSTAGE - 1) * 32);
        cp_commit();

        const uint32_t sb = sbase + (uint32_t)(i & (NSTAGE - 1)) * STAGEB;
#pragma unroll
        for (int k16 = 0; k16 < 2; k16++) {
            uint32_t a[4][4], b[4][2];
#pragma unroll
            for (int mt = 0; mt < 4; mt++)
                ldmx4(a[mt], sb + a_off + (uint32_t)(mt * 1280 + k16 * 32));
#pragma unroll
            for (int j = 0; j < 2; j++) {
                uint32_t r[4];
                ldmx4(r, sb + b_off + (uint32_t)(j * 1280 + k16 * 32));
                b[2 * j][0] = r[0]; b[2 * j][1] = r[1];
                b[2 * j + 1][0] = r[2]; b[2 * j + 1][1] = r[3];
            }
#pragma unroll
            for (int mt = 0; mt < 4; mt++)
#pragma unroll
                for (int nt = 0; nt < 4; nt++)
                    mma_f16(acc[mt][nt], a[mt][0], a[mt][1], a[mt][2], a[mt][3],
                            b[nt][0], b[nt][1]);
        }
    }

    // epilogue
#pragma unroll
    for (int mt = 0; mt < 4; mt++) {
        const int r0 = row0 + warp_m * 64 + mt * 16 + tr;
#pragma unroll
        for (int nt = 0; nt < 4; nt++) {
            const int cc = col0 + warp_n * 32 + nt * 8 + tc * 2;
            const float bx = __ldg(bias + cc), by = __ldg(bias + cc + 1);
            float2 v0 = make_float2(acc[mt][nt][0] + bx, acc[mt][nt][1] + by);
            float2 v1 = make_float2(acc[mt][nt][2] + bx, acc[mt][nt][3] + by);
            float* p0 = C + (size_t)r0 * DIMN + cc;
            float* p1 = C + (size_t)(r0 + 8) * DIMN + cc;
            if (EPI == 3) {
                float2 o0 = *(const float2*)p0;
                float2 o1 = *(const float2*)p1;
                v0.x = o0.x + 0.3f * v0.x;  v0.y = o0.y + 0.3f * v0.y;
                v1.x = o1.x + 0.3f * v1.x;  v1.y = o1.y + 0.3f * v1.y;
            }
            if (EPI != 2) {
                *(float2*)p0 = v0;
                *(float2*)p1 = v1;
            }
            if (EPI == 1 || EPI == 2) {
                __half2 h0, h1;
                h0.x = __float2half(fmaxf(v0.x, 0.f));
                h0.y = __float2half(fmaxf(v0.y, 0.f));
                h1.x = __float2half(fmaxf(v1.x, 0.f));
                h1.y = __float2half(fmaxf(v1.y, 0.f));
                *(__half2*)(H + (size_t)r0 * DIMN + cc)       = h0;
                *(__half2*)(H + (size_t)(r0 + 8) * DIMN + cc) = h1;
            }
        }
    }
}

// ---------------- per-batch tail ------------------------------------------------
__global__ void __launch_bounds__(256) final_kernel(
    const float* __restrict__ alpha_all,  // (128, 32, 20)
    const float* __restrict__ att_mask,   // (128, 1, 32)
    const float* __restrict__ ln_g, const float* __restrict__ ln_b,
    const float* __restrict__ sv_w, const float* __restrict__ sv_b,
    const float* __restrict__ ss_w, const float* __restrict__ ss_b,
    const float* __restrict__ cl_w, const float* __restrict__ cl_b,
    float* __restrict__ out)              // (128, 6)
{
    const int b    = blockIdx.x;
    const int t    = threadIdx.x;
    const int warp = t >> 5;
    const int lane = t & 31;

    __shared__ float spt [NTOP][DIMN];
    __shared__ float sagg[NTOP][DIMN];
    __shared__ float sc  [NTOP][DIMN];
    __shared__ float adj [SEQ][NTOP];
    __shared__ float sums[20];
    __shared__ int   idxs[NTOP];
    __shared__ float smask[SEQ];

    if (t < SEQ) smask[t] = att_mask[b * SEQ + t];
    __syncthreads();

    if (t < 20) {
        float s = 0.f;
        for (int si = 0; si < SEQ; si++)
            s = fmaf(alpha_all[((size_t)b * SEQ + si) * 20 + t], smask[si], s);
        sums[t] = s;
    }
    __syncthreads();

    if (t == 0) {   // lax.top_k: descending, first index on ties
        unsigned used = 0;
        for (int k = 0; k < NTOP; k++) {
            int best = 0; float bv = -3.4e38f;
            for (int p = 0; p < 20; p++)
                if (!((used >> p) & 1u) && sums[p] > bv) { bv = sums[p]; best = p; }
            used |= (1u << best);
            idxs[k] = best;
        }
    }
    __syncthreads();

    for (int i = t; i < NTOP * DIMN; i += 256) {
        const int k = i >> 9, d = i & 511;
        spt[k][d] = g_psl[((size_t)b * 20 + idxs[k]) * DIMN + d];
    }
    __syncthreads();

    for (int pair = warp; pair < SEQ * NTOP; pair += 8) {
        const int s = pair / NTOP;
        const int k = pair - s * NTOP;
        const float* xr = g_X + ((size_t)b * SEQ + s) * DIMN;
        float acc = 0.f;
        for (int d = lane; d < DIMN; d += 32)
            acc = fmaf(xr[d], spt[k][d], acc);
#pragma unroll
        for (int o = 16; o > 0; o >>= 1)
            acc += __shfl_down_sync(0xffffffffu, acc, o);
        if (lane == 0) {
            const float v = acc * 0.04419417382415922f;
            adj[s][k] = (smask[s] > 0.f) ? v : -9.0e15f;
        }
    }
    __syncthreads();

    if (warp < NTOP) {
        const int k = warp;
        float v = adj[lane][k];
        float m = v;
#pragma unroll
        for (int o = 16; o > 0; o >>= 1)
            m = fmaxf(m, __shfl_xor_sync(0xffffffffu, m, o));
        const float e = expf(v - m);
        float ss = e;
#pragma unroll
        for (int o = 16; o > 0; o >>= 1)
            ss += __shfl_xor_sync(0xffffffffu, ss, o);
        adj[lane][k] = e / ss;
    }
    __syncthreads();

    for (int d = t; d < DIMN; d += 256) {
        float a[NTOP];
#pragma unroll
        for (int k = 0; k < NTOP; k++) a[k] = 0.f;
        for (int s = 0; s < SEQ; s++) {
            const float xv = g_X[((size_t)b * SEQ + s) * DIMN + d];
#pragma unroll
            for (int k = 0; k < NTOP; k++) a[k] = fmaf(xv, adj[s][k], a[k]);
        }
#pragma unroll
        for (int k = 0; k < NTOP; k++) sagg[k][d] = a[k];
    }
    __syncthreads();

    if (warp < NTOP) {
        const int k = warp;
        float sum = 0.f, sq = 0.f;
        for (int d = lane; d < DIMN; d += 32) {
            const float v = sagg[k][d];
            sum += v;
            sq = fmaf(v, v, sq);
        }
#pragma unroll
        for (int o = 16; o > 0; o >>= 1) {
            sum += __shfl_xor_sync(0xffffffffu, sum, o);
            sq  += __shfl_xor_sync(0xffffffffu, sq,  o);
        }
        const float mu  = sum * (1.f / DIMN);
        const float var = sq * (1.f / DIMN) - mu * mu;
        const float inv = rsqrtf(var + 1e-5f);
        for (int d = lane; d < DIMN; d += 32)
            sagg[k][d] = (sagg[k][d] - mu) * inv * ln_g[d] + ln_b[d];
    }
    __syncthreads();

    for (int idx = t; idx < NTOP * DIMN; idx += 256) {
        const int k = idx >> 9, d = idx & 511;
        float accv = sv_b[d], accs = ss_b[d];
        const float4* wv = (const float4*)(sv_w + (size_t)d * DIMN);
        const float4* ws = (const float4*)(ss_w + (size_t)d * DIMN);
        const float4* pv = (const float4*)(&spt[k][0]);
        const float4* pa = (const float4*)(&sagg[k][0]);
#pragma unroll 4
        for (int e = 0; e < DIMN / 4; e++) {
            const float4 a = pv[e], w = wv[e];
            accv = fmaf(a.x, w.x, fmaf(a.y, w.y, fmaf(a.z, w.z, fmaf(a.w, w.w, accv))));
            const float4 a2 = pa[e], w2 = ws[e];
            accs = fmaf(a2.x, w2.x, fmaf(a2.y, w2.y, fmaf(a2.z, w2.z, fmaf(a2.w, w2.w, accs))));
        }
        sc[k][d] = tanhf(accv) * tanhf(accs) * cl_w[d];
    }
    __syncthreads();

    if (warp < NTOP) {
        const int k = warp;
        float s = 0.f;
        for (int d = lane; d < DIMN; d += 32) s += sc[k][d];
#pragma unroll
        for (int o = 16; o > 0; o >>= 1)
            s += __shfl_xor_sync(0xffffffffu, s, o);
        if (lane == 0) {
            const float z = s + cl_b[0];
            out[b * NTOP + k] = 1.f / (1.f + expf(-z));
        }
    }
}

// ---------------- launch ----------------------------------------------------------
extern "C" void kernel_launch(void* const* d_in, const int* in_sizes, int n_in,
                              void* d_out, int out_size)
{
    const float* inputs   = (const float*)d_in[0];
    const float* obj      = (const float*)d_in[2];
    const float* motion   = (const float*)d_in[3];
    const float* att_mask = (const float*)d_in[4];
    const float* alpha    = (const float*)d_in[5];
    const float* conv_w   = (const float*)d_in[6];
    const float* conv_b   = (const float*)d_in[7];
    const float* res_w1   = (const float*)d_in[8];
    const float* res_b1   = (const float*)d_in[9];
    const float* res_w2   = (const float*)d_in[10];
    const float* res_b2   = (const float*)d_in[11];
    const float* psl_w    = (const float*)d_in[12];
    const float* psl_b    = (const float*)d_in[13];
    const float* ln_g     = (const float*)d_in[14];
    const float* ln_b     = (const float*)d_in[15];
    const float* sv_w     = (const float*)d_in[16];
    const float* sv_b     = (const float*)d_in[17];
    const float* ss_w     = (const float*)d_in[18];
    const float* ss_b     = (const float*)d_in[19];
    const float* cl_w     = (const float*)d_in[20];
    const float* cl_b     = (const float*)d_in[21];
    float* out = (float*)d_out;

    float *X, *PSL;
    __half *Xh, *Y1h, *A, *Wc, *W1, *W2, *Wp;
    cudaGetSymbolAddress((void**)&X,   g_X);
    cudaGetSymbolAddress((void**)&Xh,  g_Xh);
    cudaGetSymbolAddress((void**)&Y1h, g_Y1h);
    cudaGetSymbolAddress((void**)&PSL, g_psl);
    cudaGetSymbolAddress((void**)&A,   g_A);
    cudaGetSymbolAddress((void**)&Wc,  g_Wc);
    cudaGetSymbolAddress((void**)&W1,  g_W1);
    cudaGetSymbolAddress((void**)&W2,  g_W2);
    cudaGetSymbolAddress((void**)&Wp,  g_Wp);

    const int SMEM_BYTES = NSTAGE * (int)STAGEB;   // 61440
    cudaFuncSetAttribute(gemm_mma<0,0>, cudaFuncAttributeMaxDynamicSharedMemorySize, SMEM_BYTES);
    cudaFuncSetAttribute(gemm_mma<0,1>, cudaFuncAttributeMaxDynamicSharedMemorySize, SMEM_BYTES);
    cudaFuncSetAttribute(gemm_mma<1,2>, cudaFuncAttributeMaxDynamicSharedMemorySize, SMEM_BYTES);
    cudaFuncSetAttribute(gemm_mma<1,3>, cudaFuncAttributeMaxDynamicSharedMemorySize, SMEM_BYTES);

    const dim3 blk(128);
    const dim3 gBig(DIMN / TILEN, 32);   // (8, 32) = 256 CTAs
    const dim3 gPsl(DIMN / TILEN, 20);   // (8, 20) = 160 CTAs

    // conversions
    f32_to_f16_pad<<<dim3((KBIGP / 8 + 255) / 256, 4096), 256>>>(inputs, A, KBIG, KBIGP);
    f32_to_f16_pad<<<dim3((KBIGP / 8 + 255) / 256, 512),  256>>>(conv_w, Wc, KBIG, KBIGP);
    reorder_w2_f16<<<(2 * 512 * KCONV + 255) / 256, 256>>>(res_w1, W1, res_w2, W2);
    f32_to_f16_pad<<<dim3((KPSL / 8 + 255) / 256, 512),   256>>>(psl_w, Wp, KPSL, KPSL);

    // GEMM1: x = inputs @ conv_w^T + conv_b ; also Xh = fp16(relu(x))
    gemm_mma<0, 1><<<gBig, blk, SMEM_BYTES>>>(A, Wc, conv_b, X, Xh, KBIGP);

    // GEMM2 (fused im2col): Y1h = fp16(relu(conv1(Xh) + b1))
    gemm_mma<1, 2><<<gBig, blk, SMEM_BYTES>>>(Xh, W1, res_b1, X /*unused*/, Y1h, KCONV);

    // GEMM3 (fused im2col): X += 0.3 * (conv2(Y1h) + b2)
    gemm_mma<1, 3><<<gBig, blk, SMEM_BYTES>>>(Y1h, W2, res_b2, X, Xh /*unused*/, KCONV);

    // concat proposals -> A ; GEMM4: psl_all
    concat_f16<<<(2560 * 128 + 255) / 256, 256>>>(obj, motion, A);
    gemm_mma<0, 0><<<gPsl, blk, SMEM_BYTES>>>(A, Wp, psl_b, PSL, Xh /*unused*/, KPSL);

    // tail
    final_kernel<<<BS_, 256>>>(alpha, att_mask, ln_g, ln_b,
                               sv_w, sv_b, ss_w, ss_b, cl_w, cl_b, out);
}

// round 8
// speedup vs baseline: 7.6028x; 1.7940x over previous
#include <cuda_runtime.h>
#include <cuda_fp16.h>
#include <math.h>
#include <stdint.h>

#define BS_    128
#define SEQ    32
#define DIMN   512
#define P_     10
#define NTOP   6

#define KBIG   10000
#define KBIGP  10016            // padded to multiple of 32
#define KCONV  2560             // 512*5 (tap-major: k = tap*512 + din)
#define KPSL   1024

// ---------------- device scratch (no allocations allowed) -------------------
__device__ float  g_X  [BS_ * SEQ * DIMN];          // x fp32 (residual + tail)
__device__ __half g_Xh [BS_ * SEQ * DIMN];          // fp16(relu(x))
__device__ __half g_Y1h[BS_ * SEQ * DIMN];          // fp16(relu(y1))
__device__ float  g_psl[BS_ * 2 * P_ * DIMN];

__device__ __half g_A  [(size_t)4096 * KBIGP];      // big activation buffer
__device__ __half g_Wc [(size_t)512 * KBIGP];
__device__ __half g_W1 [512 * KCONV];
__device__ __half g_W2 [512 * KCONV];
__device__ __half g_Wp [512 * KPSL];

// ---------------- ptx helpers -------------------------------------------------
__device__ __forceinline__ void cp16(uint32_t sa, const void* g) {
    asm volatile("cp.async.cg.shared.global [%0], [%1], 16;\n" :: "r"(sa), "l"(g) : "memory");
}
__device__ __forceinline__ void cp16z(uint32_t sa, const void* g, uint32_t srcsize) {
    asm volatile("cp.async.cg.shared.global [%0], [%1], 16, %2;\n"
                 :: "r"(sa), "l"(g), "r"(srcsize) : "memory");
}
__device__ __forceinline__ void cp_commit() {
    asm volatile("cp.async.commit_group;\n" ::: "memory");
}
template<int N> __device__ __forceinline__ void cp_wait() {
    asm volatile("cp.async.wait_group %0;\n" :: "n"(N) : "memory");
}
__device__ __forceinline__ uint32_t smem_u32(const void* p) {
    uint32_t a;
    asm("{ .reg .u64 t; cvta.to.shared.u64 t, %1; cvt.u32.u64 %0, t; }" : "=r"(a) : "l"(p));
    return a;
}
__device__ __forceinline__ void ldmx4(uint32_t* r, uint32_t addr) {
    asm volatile("ldmatrix.sync.aligned.m8n8.x4.shared.b16 {%0,%1,%2,%3}, [%4];"
                 : "=r"(r[0]), "=r"(r[1]), "=r"(r[2]), "=r"(r[3]) : "r"(addr));
}
__device__ __forceinline__ void mma_f16(float* d,
    uint32_t a0, uint32_t a1, uint32_t a2, uint32_t a3,
    uint32_t b0, uint32_t b1)
{
    asm volatile(
        "mma.sync.aligned.m16n8k16.row.col.f32.f16.f16.f32 "
        "{%0,%1,%2,%3}, {%4,%5,%6,%7}, {%8,%9}, {%0,%1,%2,%3};"
        : "+f"(d[0]), "+f"(d[1]), "+f"(d[2]), "+f"(d[3])
        : "r"(a0), "r"(a1), "r"(a2), "r"(a3), "r"(b0), "r"(b1));
}

// ---------------- conversion kernels -------------------------------------------
__global__ void __launch_bounds__(256) f32_to_f16_pad(
    const float* __restrict__ src, __half* __restrict__ dst, int K, int Kpad)
{
    const int row = blockIdx.y;
    const int c8  = (blockIdx.x * blockDim.x + threadIdx.x) << 3;
    if (c8 >= Kpad) return;
    const float* s = src + (size_t)row * K + c8;
    __half h[8];
    if (c8 + 8 <= K) {
        const float4 v0 = *(const float4*)s;
        const float4 v1 = *(const float4*)(s + 4);
        h[0] = __float2half(v0.x); h[1] = __float2half(v0.y);
        h[2] = __float2half(v0.z); h[3] = __float2half(v0.w);
        h[4] = __float2half(v1.x); h[5] = __float2half(v1.y);
        h[6] = __float2half(v1.z); h[7] = __float2half(v1.w);
    } else {
#pragma unroll
        for (int j = 0; j < 8; j++)
            h[j] = (c8 + j < K) ? __float2half(s[j]) : __float2half(0.f);
    }
    *(uint4*)(dst + (size_t)row * Kpad + c8) = *(const uint4*)h;
}

// both res weights (512, 512, 5) -> fp16 (512, 2560), k = tap*512 + din
__global__ void __launch_bounds__(256) reorder_w2_f16(
    const float* __restrict__ src1, __half* __restrict__ dst1,
    const float* __restrict__ src2, __half* __restrict__ dst2)
{
    int i = blockIdx.x * blockDim.x + threadIdx.x;
    const int n1 = 512 * KCONV;
    const float* src = (i < n1) ? src1 : src2;
    __half* dst = (i < n1) ? dst1 : dst2;
    int ii = (i < n1) ? i : i - n1;
    if (ii >= n1) return;
    int dout = ii / KCONV;
    int k    = ii - dout * KCONV;
    int tap  = k >> 9;
    int din  = k & 511;
    dst[ii] = __float2half(src[dout * KCONV + din * 5 + tap]);
}

// concat(obj, motion) -> fp16 (2560, 1024)
__global__ void __launch_bounds__(256) concat_f16(
    const float* __restrict__ obj, const float* __restrict__ motion,
    __half* __restrict__ A)
{
    int i = blockIdx.x * blockDim.x + threadIdx.x;      // 2560*128
    if (i >= 2560 * 128) return;
    int row = i >> 7;
    int c8  = (i & 127) << 3;
    int b = row / 20, p = row - b * 20;
    const float* s = (p < P_) ? obj    + ((size_t)(b * P_ + p      )) * 1024 + c8
                              : motion + ((size_t)(b * P_ + p - P_ )) * 1024 + c8;
    const float4 v0 = *(const float4*)s;
    const float4 v1 = *(const float4*)(s + 4);
    __half h[8];
    h[0] = __float2half(v0.x); h[1] = __float2half(v0.y);
    h[2] = __float2half(v0.z); h[3] = __float2half(v0.w);
    h[4] = __float2half(v1.x); h[5] = __float2half(v1.y);
    h[6] = __float2half(v1.z); h[7] = __float2half(v1.w);
    *(uint4*)(A + (size_t)row * KPSL + c8) = *(const uint4*)h;
}

// ---------------- mma.sync GEMM, 4-stage cp.async + ldmatrix -------------------
// C[M x 512] = A * B^T + bias. CTA tile 128(M) x 64(N), BK=32, 128 thr
// (4 warps as 2x2, warp tile 64x32). 4 stages = 61440 B -> 3 CTAs/SM.
#define TILEN   64
#define MATA    10240u                 // 128 rows x 80 B
#define MATBB   5120u                  // 64 rows x 80 B
#define STAGEB  (MATA + MATBB)         // 15360
#define NSTAGE  4

template<int AMODE>
__device__ __forceinline__ void load_stage(
    uint32_t sb, int t,
    const __half* __restrict__ A, const __half* __restrict__ B,
    int row0, int col0, int K, int k0)
{
#pragma unroll
    for (int j = 0; j < 4; j++) {
        const int cid = j * 128 + t;
        const int r  = cid >> 2, ch = cid & 3;
        const uint32_t sa = sb + (uint32_t)(r * 80 + ch * 16);
        if (AMODE == 0) {
            cp16(sa, A + (size_t)(row0 + r) * K + k0 + ch * 8);
        } else {
            const int grow = row0 + r;
            const int tap  = k0 >> 9;
            const int din0 = (k0 & 511) + ch * 8;
            const int s2   = (grow & 31) + tap - 2;
            const uint32_t ok = (s2 >= 0 && s2 < SEQ) ? 16u : 0u;
            const int srow = ok ? (grow + tap - 2) : grow;
            cp16z(sa, A + (size_t)srow * DIMN + din0, ok);
        }
    }
#pragma unroll
    for (int j = 0; j < 2; j++) {
        const int cid = j * 128 + t;
        const int r  = cid >> 2, ch = cid & 3;
        cp16(sb + MATA + (uint32_t)(r * 80 + ch * 16),
             B + (size_t)(col0 + r) * K + k0 + ch * 8);
    }
}

template<int AMODE, int EPI>
__global__ void __launch_bounds__(128, 3) gemm_mma(
    const __half* __restrict__ A, const __half* __restrict__ B,
    const float* __restrict__ bias, float* __restrict__ C,
    __half* __restrict__ H, int K)
{
    extern __shared__ char smem[];
    const uint32_t sbase = smem_u32(smem);
    const int t = threadIdx.x;
    const int wid = t >> 5, lane = t & 31;
    const int warp_m = wid >> 1, warp_n = wid & 1;
    const int tr = lane >> 2, tc = lane & 3;
    const int row0 = blockIdx.y * 128;
    const int col0 = blockIdx.x * TILEN;

    const uint32_t a_off = (uint32_t)((warp_m * 64 + (lane & 15)) * 80 + (lane >> 4) * 16);
    const uint32_t b_off = MATA +
        (uint32_t)((warp_n * 32 + (lane & 7) + ((lane >> 4) << 3)) * 80 + ((lane >> 3) & 1) * 16);

    float acc[4][4][4];
#pragma unroll
    for (int i = 0; i < 4; i++)
#pragma unroll
        for (int j = 0; j < 4; j++)
#pragma unroll
            for (int e = 0; e < 4; e++) acc[i][j][e] = 0.f;

    const int nch = K >> 5;

#pragma unroll
    for (int s = 0; s < NSTAGE - 1; s++) {
        if (s < nch)
            load_stage<AMODE>(sbase + s * STAGEB, t, A, B, row0, col0, K, s * 32);
        cp_commit();
    }

    for (int i = 0; i < nch; i++) {
        cp_wait<NSTAGE - 2>();
        __syncthreads();

        if (i + NSTAGE - 1 < nch)
            load_stage<AMODE>(sbase + ((i + NSTAGE - 1) & (NSTAGE - 1)) * STAGEB,
                              t, A, B, row0, col0, K, (i + NSTAGE - 1) * 32);
        cp_commit();

        const uint32_t sb = sbase + (uint32_t)(i & (NSTAGE - 1)) * STAGEB;
#pragma unroll
        for (int k16 = 0; k16 < 2; k16++) {
            uint32_t a[4][4], b[4][2];
#pragma unroll
            for (int mt = 0; mt < 4; mt++)
                ldmx4(a[mt], sb + a_off + (uint32_t)(mt * 1280 + k16 * 32));
#pragma unroll
            for (int j = 0; j < 2; j++) {
                uint32_t r[4];
                ldmx4(r, sb + b_off + (uint32_t)(j * 1280 + k16 * 32));
                b[2 * j][0] = r[0]; b[2 * j][1] = r[1];
                b[2 * j + 1][0] = r[2]; b[2 * j + 1][1] = r[3];
            }
#pragma unroll
            for (int mt = 0; mt < 4; mt++)
#pragma unroll
                for (int nt = 0; nt < 4; nt++)
                    mma_f16(acc[mt][nt], a[mt][0], a[mt][1], a[mt][2], a[mt][3],
                            b[nt][0], b[nt][1]);
        }
    }

    // epilogue
#pragma unroll
    for (int mt = 0; mt < 4; mt++) {
        const int r0 = row0 + warp_m * 64 + mt * 16 + tr;
#pragma unroll
        for (int nt = 0; nt < 4; nt++) {
            const int cc = col0 + warp_n * 32 + nt * 8 + tc * 2;
            const float bx = __ldg(bias + cc), by = __ldg(bias + cc + 1);
            float2 v0 = make_float2(acc[mt][nt][0] + bx, acc[mt][nt][1] + by);
            float2 v1 = make_float2(acc[mt][nt][2] + bx, acc[mt][nt][3] + by);
            float* p0 = C + (size_t)r0 * DIMN + cc;
            float* p1 = C + (size_t)(r0 + 8) * DIMN + cc;
            if (EPI == 3) {
                float2 o0 = *(const float2*)p0;
                float2 o1 = *(const float2*)p1;
                v0.x = o0.x + 0.3f * v0.x;  v0.y = o0.y + 0.3f * v0.y;
                v1.x = o1.x + 0.3f * v1.x;  v1.y = o1.y + 0.3f * v1.y;
            }
            if (EPI != 2) {
                *(float2*)p0 = v0;
                *(float2*)p1 = v1;
            }
            if (EPI == 1 || EPI == 2) {
                __half2 h0, h1;
                h0.x = __float2half(fmaxf(v0.x, 0.f));
                h0.y = __float2half(fmaxf(v0.y, 0.f));
                h1.x = __float2half(fmaxf(v1.x, 0.f));
                h1.y = __float2half(fmaxf(v1.y, 0.f));
                *(__half2*)(H + (size_t)r0 * DIMN + cc)       = h0;
                *(__half2*)(H + (size_t)(r0 + 8) * DIMN + cc) = h1;
            }
        }
    }
}

// ---------------- per-batch tail ------------------------------------------------
__global__ void __launch_bounds__(256) final_kernel(
    const float* __restrict__ alpha_all,  // (128, 32, 20)
    const float* __restrict__ att_mask,   // (128, 1, 32)
    const float* __restrict__ ln_g, const float* __restrict__ ln_b,
    const float* __restrict__ sv_w, const float* __restrict__ sv_b,
    const float* __restrict__ ss_w, const float* __restrict__ ss_b,
    const float* __restrict__ cl_w, const float* __restrict__ cl_b,
    float* __restrict__ out)              // (128, 6)
{
    const int b    = blockIdx.x;
    const int t    = threadIdx.x;
    const int warp = t >> 5;
    const int lane = t & 31;

    __shared__ float spt [NTOP][DIMN];
    __shared__ float sagg[NTOP][DIMN];
    __shared__ float sc  [NTOP][DIMN];
    __shared__ float adj [SEQ][NTOP];
    __shared__ float sums[20];
    __shared__ int   idxs[NTOP];
    __shared__ float smask[SEQ];

    if (t < SEQ) smask[t] = att_mask[b * SEQ + t];
    __syncthreads();

    if (t < 20) {
        float s = 0.f;
        for (int si = 0; si < SEQ; si++)
            s = fmaf(alpha_all[((size_t)b * SEQ + si) * 20 + t], smask[si], s);
        sums[t] = s;
    }
    __syncthreads();

    if (t == 0) {   // lax.top_k: descending, first index on ties
        unsigned used = 0;
        for (int k = 0; k < NTOP; k++) {
            int best = 0; float bv = -3.4e38f;
            for (int p = 0; p < 20; p++)
                if (!((used >> p) & 1u) && sums[p] > bv) { bv = sums[p]; best = p; }
            used |= (1u << best);
            idxs[k] = best;
        }
    }
    __syncthreads();

    for (int i = t; i < NTOP * DIMN; i += 256) {
        const int k = i >> 9, d = i & 511;
        spt[k][d] = g_psl[((size_t)b * 20 + idxs[k]) * DIMN + d];
    }
    __syncthreads();

    for (int pair = warp; pair < SEQ * NTOP; pair += 8) {
        const int s = pair / NTOP;
        const int k = pair - s * NTOP;
        const float* xr = g_X + ((size_t)b * SEQ + s) * DIMN;
        float acc = 0.f;
        for (int d = lane; d < DIMN; d += 32)
            acc = fmaf(xr[d], spt[k][d], acc);
#pragma unroll
        for (int o = 16; o > 0; o >>= 1)
            acc += __shfl_down_sync(0xffffffffu, acc, o);
        if (lane == 0) {
            const float v = acc * 0.04419417382415922f;
            adj[s][k] = (smask[s] > 0.f) ? v : -9.0e15f;
        }
    }
    __syncthreads();

    if (warp < NTOP) {
        const int k = warp;
        float v = adj[lane][k];
        float m = v;
#pragma unroll
        for (int o = 16; o > 0; o >>= 1)
            m = fmaxf(m, __shfl_xor_sync(0xffffffffu, m, o));
        const float e = expf(v - m);
        float ss = e;
#pragma unroll
        for (int o = 16; o > 0; o >>= 1)
            ss += __shfl_xor_sync(0xffffffffu, ss, o);
        adj[lane][k] = e / ss;
    }
    __syncthreads();

    for (int d = t; d < DIMN; d += 256) {
        float a[NTOP];
#pragma unroll
        for (int k = 0; k < NTOP; k++) a[k] = 0.f;
        for (int s = 0; s < SEQ; s++) {
            const float xv = g_X[((size_t)b * SEQ + s) * DIMN + d];
#pragma unroll
            for (int k = 0; k < NTOP; k++) a[k] = fmaf(xv, adj[s][k], a[k]);
        }
#pragma unroll
        for (int k = 0; k < NTOP; k++) sagg[k][d] = a[k];
    }
    __syncthreads();

    if (warp < NTOP) {
        const int k = warp;
        float sum = 0.f, sq = 0.f;
        for (int d = lane; d < DIMN; d += 32) {
            const float v = sagg[k][d];
            sum += v;
            sq = fmaf(v, v, sq);
        }
#pragma unroll
        for (int o = 16; o > 0; o >>= 1) {
            sum += __shfl_xor_sync(0xffffffffu, sum, o);
            sq  += __shfl_xor_sync(0xffffffffu, sq,  o);
        }
        const float mu  = sum * (1.f / DIMN);
        const float var = sq * (1.f / DIMN) - mu * mu;
        const float inv = rsqrtf(var + 1e-5f);
        for (int d = lane; d < DIMN; d += 32)
            sagg[k][d] = (sagg[k][d] - mu) * inv * ln_g[d] + ln_b[d];
    }
    __syncthreads();

    // v/s GEMVs, d-major: thread owns d = 2t, 2t+1; each weight row read ONCE,
    // all 6 k accumulated in registers (6x less L2 traffic than k-major).
    {
        const int d = t * 2;
        float accv[2][NTOP], accs[2][NTOP];
#pragma unroll
        for (int j = 0; j < 2; j++)
#pragma unroll
            for (int k = 0; k < NTOP; k++) {
                accv[j][k] = sv_b[d + j];
                accs[j][k] = ss_b[d + j];
            }
        const float4* wv0 = (const float4*)(sv_w + (size_t)d * DIMN);
        const float4* wv1 = (const float4*)(sv_w + (size_t)(d + 1) * DIMN);
        const float4* ws0 = (const float4*)(ss_w + (size_t)d * DIMN);
        const float4* ws1 = (const float4*)(ss_w + (size_t)(d + 1) * DIMN);
#pragma unroll 2
        for (int e = 0; e < DIMN / 4; e++) {
            const float4 v0 = wv0[e], v1 = wv1[e];
            const float4 s0 = ws0[e], s1 = ws1[e];
#pragma unroll
            for (int k = 0; k < NTOP; k++) {
                const float4 a = *(const float4*)(&spt[k][e * 4]);
                const float4 g = *(const float4*)(&sagg[k][e * 4]);
                accv[0][k] = fmaf(a.x, v0.x, fmaf(a.y, v0.y, fmaf(a.z, v0.z, fmaf(a.w, v0.w, accv[0][k]))));
                accv[1][k] = fmaf(a.x, v1.x, fmaf(a.y, v1.y, fmaf(a.z, v1.z, fmaf(a.w, v1.w, accv[1][k]))));
                accs[0][k] = fmaf(g.x, s0.x, fmaf(g.y, s0.y, fmaf(g.z, s0.z, fmaf(g.w, s0.w, accs[0][k]))));
                accs[1][k] = fmaf(g.x, s1.x, fmaf(g.y, s1.y, fmaf(g.z, s1.z, fmaf(g.w, s1.w, accs[1][k]))));
            }
        }
#pragma unroll
        for (int j = 0; j < 2; j++) {
            const float cw = cl_w[d + j];
#pragma unroll
            for (int k = 0; k < NTOP; k++)
                sc[k][d + j] = tanhf(accv[j][k]) * tanhf(accs[j][k]) * cw;
        }
    }
    __syncthreads();

    if (warp < NTOP) {
        const int k = warp;
        float s = 0.f;
        for (int d = lane; d < DIMN; d += 32) s += sc[k][d];
#pragma unroll
        for (int o = 16; o > 0; o >>= 1)
            s += __shfl_xor_sync(0xffffffffu, s, o);
        if (lane == 0) {
            const float z = s + cl_b[0];
            out[b * NTOP + k] = 1.f / (1.f + expf(-z));
        }
    }
}

// ---------------- launch ----------------------------------------------------------
extern "C" void kernel_launch(void* const* d_in, const int* in_sizes, int n_in,
                              void* d_out, int out_size)
{
    const float* inputs   = (const float*)d_in[0];
    const float* obj      = (const float*)d_in[2];
    const float* motion   = (const float*)d_in[3];
    const float* att_mask = (const float*)d_in[4];
    const float* alpha    = (const float*)d_in[5];
    const float* conv_w   = (const float*)d_in[6];
    const float* conv_b   = (const float*)d_in[7];
    const float* res_w1   = (const float*)d_in[8];
    const float* res_b1   = (const float*)d_in[9];
    const float* res_w2   = (const float*)d_in[10];
    const float* res_b2   = (const float*)d_in[11];
    const float* psl_w    = (const float*)d_in[12];
    const float* psl_b    = (const float*)d_in[13];
    const float* ln_g     = (const float*)d_in[14];
    const float* ln_b     = (const float*)d_in[15];
    const float* sv_w     = (const float*)d_in[16];
    const float* sv_b     = (const float*)d_in[17];
    const float* ss_w     = (const float*)d_in[18];
    const float* ss_b     = (const float*)d_in[19];
    const float* cl_w     = (const float*)d_in[20];
    const float* cl_b     = (const float*)d_in[21];
    float* out = (float*)d_out;

    float *X, *PSL;
    __half *Xh, *Y1h, *A, *Wc, *W1, *W2, *Wp;
    cudaGetSymbolAddress((void**)&X,   g_X);
    cudaGetSymbolAddress((void**)&Xh,  g_Xh);
    cudaGetSymbolAddress((void**)&Y1h, g_Y1h);
    cudaGetSymbolAddress((void**)&PSL, g_psl);
    cudaGetSymbolAddress((void**)&A,   g_A);
    cudaGetSymbolAddress((void**)&Wc,  g_Wc);
    cudaGetSymbolAddress((void**)&W1,  g_W1);
    cudaGetSymbolAddress((void**)&W2,  g_W2);
    cudaGetSymbolAddress((void**)&Wp,  g_Wp);

    const int SMEM_BYTES = NSTAGE * (int)STAGEB;   // 61440
    cudaFuncSetAttribute(gemm_mma<0,0>, cudaFuncAttributeMaxDynamicSharedMemorySize, SMEM_BYTES);
    cudaFuncSetAttribute(gemm_mma<0,1>, cudaFuncAttributeMaxDynamicSharedMemorySize, SMEM_BYTES);
    cudaFuncSetAttribute(gemm_mma<1,2>, cudaFuncAttributeMaxDynamicSharedMemorySize, SMEM_BYTES);
    cudaFuncSetAttribute(gemm_mma<1,3>, cudaFuncAttributeMaxDynamicSharedMemorySize, SMEM_BYTES);

    const dim3 blk(128);
    const dim3 gBig(DIMN / TILEN, 32);   // (8, 32) = 256 CTAs
    const dim3 gPsl(DIMN / TILEN, 20);   // (8, 20) = 160 CTAs

    // #0..#2: conversions needed by GEMM1/2/3
    f32_to_f16_pad<<<dim3((KBIGP / 8 + 255) / 256, 4096), 256>>>(inputs, A, KBIG, KBIGP);
    f32_to_f16_pad<<<dim3((KBIGP / 8 + 255) / 256, 512),  256>>>(conv_w, Wc, KBIG, KBIGP);
    reorder_w2_f16<<<(2 * 512 * KCONV + 255) / 256, 256>>>(res_w1, W1, res_w2, W2);

    // #3: GEMM1 (lands at the ncu-profiled launch slot)
    gemm_mma<0, 1><<<gBig, blk, SMEM_BYTES>>>(A, Wc, conv_b, X, Xh, KBIGP);

    // #4: GEMM2 (fused im2col): Y1h = fp16(relu(conv1(Xh) + b1))
    gemm_mma<1, 2><<<gBig, blk, SMEM_BYTES>>>(Xh, W1, res_b1, X /*unused*/, Y1h, KCONV);

    // #5: GEMM3 (fused im2col): X += 0.3 * (conv2(Y1h) + b2)
    gemm_mma<1, 3><<<gBig, blk, SMEM_BYTES>>>(Y1h, W2, res_b2, X, Xh /*unused*/, KCONV);

    // #6..#8: psl path (A reused after GEMM1 is done)
    f32_to_f16_pad<<<dim3((KPSL / 8 + 255) / 256, 512), 256>>>(psl_w, Wp, KPSL, KPSL);
    concat_f16<<<(2560 * 128 + 255) / 256, 256>>>(obj, motion, A);
    gemm_mma<0, 0><<<gPsl, blk, SMEM_BYTES>>>(A, Wp, psl_b, PSL, Xh /*unused*/, KPSL);

    // #9: tail
    final_kernel<<<BS_, 256>>>(alpha, att_mask, ln_g, ln_b,
                               sv_w, sv_b, ss_w, ss_b, cl_w, cl_b, out);
}